// round 1
// baseline (speedup 1.0000x reference)
#include <cuda_runtime.h>
#include <cstdint>

#define BATCH    1024
#define EMBED    128
#define ITEMS    262144
#define TOPK     100

// 1 GiB scratch for logits (static __device__ — allocation-free rule)
__device__ float g_logits[(size_t)BATCH * ITEMS];

// ---------------------------------------------------------------------------
// GEMM: logits[b][n] = dot(x[b], w[n]);  M=1024, N=262144, K=128
// CTA tile 128x128, BK=32, 256 threads, 8x8 micro-tile per thread.
// ---------------------------------------------------------------------------
#define BM   128
#define BN   128
#define BK   32
#define TPAD 132   // 132*4 = 528 bytes, multiple of 16 -> float4-aligned rows

__global__ __launch_bounds__(256, 2)
void gemm_kernel(const float* __restrict__ x, const float* __restrict__ w)
{
    __shared__ float As[BK][TPAD];   // As[k][m]
    __shared__ float Bs[BK][TPAD];   // Bs[k][n]

    const int tid = threadIdx.x;
    const int tx  = tid & 15;        // 0..15 (item micro-col)
    const int ty  = tid >> 4;        // 0..15 (row micro-row)
    const int rowBase = blockIdx.y * BM;
    const int colBase = blockIdx.x * BN;

    const float4* x4 = reinterpret_cast<const float4*>(x + (size_t)rowBase * EMBED);
    const float4* w4 = reinterpret_cast<const float4*>(w + (size_t)colBase * EMBED);

    float acc[8][8];
    #pragma unroll
    for (int i = 0; i < 8; i++)
        #pragma unroll
        for (int j = 0; j < 8; j++) acc[i][j] = 0.0f;

    #pragma unroll
    for (int k0 = 0; k0 < EMBED; k0 += BK) {
        const int k0_4 = k0 >> 2;
        // Stage A and B tiles (transposed to [k][m]) — 1024 float4 each.
        #pragma unroll
        for (int it = 0; it < 4; it++) {
            int f  = tid + 256 * it;     // 0..1023
            int m  = f >> 3;             // 0..127
            int kq = f & 7;              // 0..7 -> k = 4*kq + j
            float4 va = x4[(size_t)m * (EMBED / 4) + k0_4 + kq];
            As[4 * kq + 0][m] = va.x;
            As[4 * kq + 1][m] = va.y;
            As[4 * kq + 2][m] = va.z;
            As[4 * kq + 3][m] = va.w;
            float4 vb = w4[(size_t)m * (EMBED / 4) + k0_4 + kq];
            Bs[4 * kq + 0][m] = vb.x;
            Bs[4 * kq + 1][m] = vb.y;
            Bs[4 * kq + 2][m] = vb.z;
            Bs[4 * kq + 3][m] = vb.w;
        }
        __syncthreads();

        #pragma unroll
        for (int kk = 0; kk < BK; kk++) {
            float4 a0 = *reinterpret_cast<const float4*>(&As[kk][ty * 8 + 0]);
            float4 a1 = *reinterpret_cast<const float4*>(&As[kk][ty * 8 + 4]);
            float4 b0 = *reinterpret_cast<const float4*>(&Bs[kk][tx * 8 + 0]);
            float4 b1 = *reinterpret_cast<const float4*>(&Bs[kk][tx * 8 + 4]);
            float a[8] = {a0.x, a0.y, a0.z, a0.w, a1.x, a1.y, a1.z, a1.w};
            float b[8] = {b0.x, b0.y, b0.z, b0.w, b1.x, b1.y, b1.z, b1.w};
            #pragma unroll
            for (int i = 0; i < 8; i++)
                #pragma unroll
                for (int j = 0; j < 8; j++)
                    acc[i][j] = fmaf(a[i], b[j], acc[i][j]);
        }
        __syncthreads();
    }

    // Epilogue: write 8x8 tile, float4-coalesced.
    #pragma unroll
    for (int i = 0; i < 8; i++) {
        int r = rowBase + ty * 8 + i;
        float* dst = g_logits + (size_t)r * ITEMS + colBase + tx * 8;
        float4 v0 = make_float4(acc[i][0], acc[i][1], acc[i][2], acc[i][3]);
        float4 v1 = make_float4(acc[i][4], acc[i][5], acc[i][6], acc[i][7]);
        reinterpret_cast<float4*>(dst)[0] = v0;
        reinterpret_cast<float4*>(dst)[1] = v1;
    }
}

// ---------------------------------------------------------------------------
// Exact top-100 per row. 1 CTA (512 threads) per row.
// Phase 1: per-thread max over strided slice -> sort 512 maxima -> t = [99].
//          (threshold is a LOWER bound on the true 100th value: guaranteed
//           count(v >= t) >= 100; statistically ~111.)
// Phase 2: collect all (v >= t) as 64-bit keys (sortval<<32)|~idx.
// Phase 3: bitonic sort descending -> value desc, index asc on ties (matches
//          jax.lax.top_k tie order). Emit first 100 indices as float.
// ---------------------------------------------------------------------------
#define TOPK_THREADS 512
#define CAND_MAX     4096

__device__ __forceinline__ unsigned int fkey(float f)
{
    unsigned int b = __float_as_uint(f);
    return b ^ ((b & 0x80000000u) ? 0xFFFFFFFFu : 0x80000000u);
}

__global__ __launch_bounds__(TOPK_THREADS)
void topk_kernel(float* __restrict__ out)
{
    __shared__ float              s_max[TOPK_THREADS];
    __shared__ unsigned long long s_cand[CAND_MAX];
    __shared__ int                s_cnt;
    __shared__ float              s_thresh;

    const int row = blockIdx.x;
    const int tid = threadIdx.x;
    const float4* lg4 = reinterpret_cast<const float4*>(g_logits + (size_t)row * ITEMS);
    const int NF4 = ITEMS / 4;   // 65536

    // Phase 1: strided max
    float m = -3.402823466e+38f;
    for (int f = tid; f < NF4; f += TOPK_THREADS) {
        float4 v = lg4[f];
        m = fmaxf(m, fmaxf(fmaxf(v.x, v.y), fmaxf(v.z, v.w)));
    }
    s_max[tid] = m;
    __syncthreads();

    // Bitonic sort 512 floats, descending
    for (int k = 2; k <= TOPK_THREADS; k <<= 1) {
        for (int j = k >> 1; j > 0; j >>= 1) {
            int ixj = tid ^ j;
            if (ixj > tid) {
                bool desc = ((tid & k) == 0);
                float a = s_max[tid], b = s_max[ixj];
                if (desc ? (a < b) : (a > b)) { s_max[tid] = b; s_max[ixj] = a; }
            }
            __syncthreads();
        }
    }
    if (tid == 0) { s_thresh = s_max[TOPK - 1]; s_cnt = 0; }
    __syncthreads();
    const float t = s_thresh;

    // Phase 2: collect candidates >= t
    for (int f = tid; f < NF4; f += TOPK_THREADS) {
        float4 v = lg4[f];
        float vv[4] = {v.x, v.y, v.z, v.w};
        int base = f * 4;
        #pragma unroll
        for (int l = 0; l < 4; l++) {
            if (vv[l] >= t) {
                int p = atomicAdd(&s_cnt, 1);
                if (p < CAND_MAX) {
                    unsigned long long key =
                        ((unsigned long long)fkey(vv[l]) << 32) |
                        (unsigned int)(~(unsigned int)(base + l));
                    s_cand[p] = key;
                }
            }
        }
    }
    __syncthreads();

    int cnt = s_cnt < CAND_MAX ? s_cnt : CAND_MAX;
    int P = 128;
    while (P < cnt) P <<= 1;
    for (int i = tid; i < P; i += TOPK_THREADS)
        if (i >= cnt) s_cand[i] = 0ULL;
    __syncthreads();

    // Bitonic sort P 64-bit keys, descending
    for (int k = 2; k <= P; k <<= 1) {
        for (int j = k >> 1; j > 0; j >>= 1) {
            for (int i = tid; i < P; i += TOPK_THREADS) {
                int ixj = i ^ j;
                if (ixj > i) {
                    bool desc = ((i & k) == 0);
                    unsigned long long a = s_cand[i], b = s_cand[ixj];
                    if (desc ? (a < b) : (a > b)) { s_cand[i] = b; s_cand[ixj] = a; }
                }
            }
            __syncthreads();
        }
    }

    if (tid < TOPK) {
        unsigned int low = (unsigned int)s_cand[tid];
        out[(size_t)row * TOPK + tid] = (float)(~low);
    }
}

// ---------------------------------------------------------------------------
extern "C" void kernel_launch(void* const* d_in, const int* in_sizes, int n_in,
                              void* d_out, int out_size)
{
    const float* x = nullptr;
    const float* w = nullptr;
    for (int i = 0; i < n_in; i++) {
        if (in_sizes[i] == BATCH * EMBED)      x = (const float*)d_in[i];
        else if (in_sizes[i] == ITEMS * EMBED) w = (const float*)d_in[i];
    }
    float* out = (float*)d_out;

    dim3 grid(ITEMS / BN, BATCH / BM);
    gemm_kernel<<<grid, 256>>>(x, w);
    topk_kernel<<<BATCH, TOPK_THREADS>>>(out);
}

// round 4
// speedup vs baseline: 2.6011x; 2.6011x over previous
#include <cuda_runtime.h>
#include <cuda_bf16.h>
#include <cstdint>

#define BATCH    1024
#define EMBED    128
#define ITEMS    262144
#define TOPK     100
#define TM       32               // tile-max granularity (items)
#define NTM      (ITEMS/TM)       // 8192 tile maxima per row

// 512MB bf16 screening logits + 32MB fp32 tile maxima (static: allocation-free)
__device__ __nv_bfloat16 g_logits[(size_t)BATCH * ITEMS];
__device__ float         g_tilemax[(size_t)BATCH * NTM];

// ---------------------------------------------------------------------------
__device__ __forceinline__ uint32_t smem_u32(const void* p) {
    uint32_t a;
    asm("{ .reg .u64 t; cvta.to.shared.u64 t, %1; cvt.u32.u64 %0, t; }"
        : "=r"(a) : "l"(p));
    return a;
}
__device__ __forceinline__ uint32_t packbf(float lo, float hi) {
    uint32_t r;
    asm("cvt.rn.bf16x2.f32 %0, %1, %2;" : "=r"(r) : "f"(hi), "f"(lo));
    return r;
}

#define LDSM4(r0, r1, r2, r3, a)                                              \
    asm volatile("ldmatrix.sync.aligned.m8n8.x4.shared.b16 {%0,%1,%2,%3}, [%4];" \
        : "=r"(r0), "=r"(r1), "=r"(r2), "=r"(r3) : "r"(a))

#define MMA_BF16(d, A, b0, b1)                                                \
    asm volatile("mma.sync.aligned.m16n8k16.row.col.f32.bf16.bf16.f32 "       \
        "{%0,%1,%2,%3}, {%4,%5,%6,%7}, {%8,%9}, {%0,%1,%2,%3};"               \
        : "+f"((d)[0]), "+f"((d)[1]), "+f"((d)[2]), "+f"((d)[3])              \
        : "r"((A)[0]), "r"((A)[1]), "r"((A)[2]), "r"((A)[3]),                 \
          "r"(b0), "r"(b1))

// ---------------------------------------------------------------------------
// Screening GEMM: bf16 HMMA, CTA 128(M) x 128(N), K=128 single-shot in smem.
// 8 warps in 2(M) x 4(N) grid; warp tile 64x32 = 4x4 m16n8k16 atoms.
// Writes bf16 logits + fp32 tile maxima (one 32-item group per warp column).
// ---------------------------------------------------------------------------
__global__ __launch_bounds__(256)
void gemm_screen(const float* __restrict__ x, const float* __restrict__ w)
{
    extern __shared__ char smem[];
    const uint32_t sb = smem_u32(smem);
    const int tid  = threadIdx.x;
    const int lane = tid & 31;
    const int wid  = tid >> 5;
    const int nBase   = blockIdx.x * 128;
    const int rowBase = blockIdx.y * 128;

    // ---- Stage: fp32 -> bf16, 16B chunks, chunk-XOR swizzle ----
    const float4* x4 = (const float4*)(x + (size_t)rowBase * EMBED);
    const float4* w4 = (const float4*)(w + (size_t)nBase * EMBED);
    #pragma unroll
    for (int i = 0; i < 8; i++) {
        const int flat = tid + 256 * i;          // 0..2047 chunks
        const int r = flat >> 4, c = flat & 15;
        const int swc = c ^ (r & 7);
        float4 a0 = x4[flat * 2], a1 = x4[flat * 2 + 1];
        uint4 pa = make_uint4(packbf(a0.x, a0.y), packbf(a0.z, a0.w),
                              packbf(a1.x, a1.y), packbf(a1.z, a1.w));
        *(uint4*)(smem + r * 256 + swc * 16) = pa;
        float4 b0 = w4[flat * 2], b1 = w4[flat * 2 + 1];
        uint4 pb = make_uint4(packbf(b0.x, b0.y), packbf(b0.z, b0.w),
                              packbf(b1.x, b1.y), packbf(b1.z, b1.w));
        *(uint4*)(smem + 32768 + r * 256 + swc * 16) = pb;
    }
    __syncthreads();

    // ---- Compute ----
    const int wm = wid >> 2;          // 0..1
    const int wn = wid & 3;           // 0..3
    const int la7  = lane & 7;
    const int lg8  = (lane >> 3) & 1;
    const int cgrp = lane >> 4;       // chunk group 0/1 -> k halves

    int Aoff[4], Asw[4];
    #pragma unroll
    for (int a = 0; a < 4; a++) {
        const int rr = wm * 64 + a * 16 + la7 + lg8 * 8;
        Aoff[a] = rr * 256;  Asw[a] = rr & 7;
    }
    int Boff[2], Bsw[2];
    #pragma unroll
    for (int p = 0; p < 2; p++) {
        const int nr = wn * 32 + p * 16 + la7 + lg8 * 8;
        Boff[p] = 32768 + nr * 256;  Bsw[p] = nr & 7;
    }

    float d[4][4][4];
    #pragma unroll
    for (int a = 0; a < 4; a++)
        #pragma unroll
        for (int b = 0; b < 4; b++)
            #pragma unroll
            for (int q = 0; q < 4; q++) d[a][b][q] = 0.0f;

    #pragma unroll
    for (int ks = 0; ks < 8; ks++) {
        const int kc = ks * 2 + cgrp;
        uint32_t A[4][4], B[2][4];
        #pragma unroll
        for (int a = 0; a < 4; a++)
            LDSM4(A[a][0], A[a][1], A[a][2], A[a][3],
                  sb + Aoff[a] + ((kc ^ Asw[a]) << 4));
        #pragma unroll
        for (int p = 0; p < 2; p++)
            LDSM4(B[p][0], B[p][1], B[p][2], B[p][3],
                  sb + Boff[p] + ((kc ^ Bsw[p]) << 4));
        #pragma unroll
        for (int a = 0; a < 4; a++)
            #pragma unroll
            for (int b = 0; b < 4; b++)
                MMA_BF16(d[a][b], A[a], B[b >> 1][b & 1], B[b >> 1][(b & 1) + 2]);
    }

    // ---- Epilogue: bf16 logits + tile maxima ----
    const int colW = nBase + wn * 32;            // warp's 32-item group start
    #pragma unroll
    for (int a = 0; a < 4; a++) {
        const int r1 = rowBase + wm * 64 + a * 16 + (lane >> 2);
        const int r2 = r1 + 8;
        float m1 = -3.402823466e+38f, m2 = m1;
        #pragma unroll
        for (int b = 0; b < 4; b++) {
            const int col = colW + b * 8 + 2 * (lane & 3);
            *(uint32_t*)((char*)g_logits + ((size_t)r1 * ITEMS + col) * 2) =
                packbf(d[a][b][0], d[a][b][1]);
            *(uint32_t*)((char*)g_logits + ((size_t)r2 * ITEMS + col) * 2) =
                packbf(d[a][b][2], d[a][b][3]);
            m1 = fmaxf(m1, fmaxf(d[a][b][0], d[a][b][1]));
            m2 = fmaxf(m2, fmaxf(d[a][b][2], d[a][b][3]));
        }
        m1 = fmaxf(m1, __shfl_xor_sync(0xFFFFFFFFu, m1, 1));
        m1 = fmaxf(m1, __shfl_xor_sync(0xFFFFFFFFu, m1, 2));
        m2 = fmaxf(m2, __shfl_xor_sync(0xFFFFFFFFu, m2, 1));
        m2 = fmaxf(m2, __shfl_xor_sync(0xFFFFFFFFu, m2, 2));
        if ((lane & 3) == 0) {
            const int grp = colW / TM;
            g_tilemax[(size_t)r1 * NTM + grp] = m1;
            g_tilemax[(size_t)r2 * NTM + grp] = m2;
        }
    }
}

// ---------------------------------------------------------------------------
// Top-k: threshold from tile maxima, candidate collection with rigorous
// bf16-error margin, rescoring in REFERENCE-matching order (sequential fmaf
// over k=0..127 per candidate — bit-identical to the round-1 kernel that
// produced rel_err 0.0), bitonic sort of 64-bit keys.
// ---------------------------------------------------------------------------
#define TKT 512

__device__ __forceinline__ unsigned int fkey(float f) {
    unsigned int b = __float_as_uint(f);
    return b ^ ((b & 0x80000000u) ? 0xFFFFFFFFu : 0x80000000u);
}

__global__ __launch_bounds__(TKT)
void topk_kernel(const float* __restrict__ x, const float* __restrict__ w,
                 float* __restrict__ out)
{
    __shared__ float              s_x[EMBED];
    __shared__ float              s_max[TKT];
    __shared__ int                s_tiles[2048];
    __shared__ int                s_cidx[2048];
    __shared__ unsigned long long s_cand[2048];
    __shared__ int   s_nt, s_nc;
    __shared__ float s_eps;

    const int row = blockIdx.x;
    const int tid = threadIdx.x;
    const float* tm = g_tilemax + (size_t)row * NTM;

    if (tid < EMBED) s_x[tid] = x[(size_t)row * EMBED + tid];
    if (tid == 0) { s_nt = 0; s_nc = 0; }
    __syncthreads();

    // eps = 1.05 * 2^-7 * ||x||2 * (0.1*sqrt(128))
    if (tid < 32) {
        float ss = 0.0f;
        #pragma unroll
        for (int j = 0; j < 4; j++) { float v = s_x[tid * 4 + j]; ss += v * v; }
        #pragma unroll
        for (int o = 16; o > 0; o >>= 1) ss += __shfl_xor_sync(0xFFFFFFFFu, ss, o);
        if (tid == 0) s_eps = 1.05f * (1.0f / 128.0f) * sqrtf(ss) * 1.1313708f;
    }

    // group maxima over tile maxima (16 per thread, coalesced strided)
    float m = -3.402823466e+38f;
    #pragma unroll
    for (int j = 0; j < 16; j++) m = fmaxf(m, tm[tid + TKT * j]);
    s_max[tid] = m;
    __syncthreads();

    for (int k = 2; k <= TKT; k <<= 1) {
        for (int j = k >> 1; j > 0; j >>= 1) {
            const int ixj = tid ^ j;
            if (ixj > tid) {
                const bool desc = ((tid & k) == 0);
                const float a = s_max[tid], b = s_max[ixj];
                if (desc ? (a < b) : (a > b)) { s_max[tid] = b; s_max[ixj] = a; }
            }
            __syncthreads();
        }
    }
    const float t    = s_max[TOPK - 1];
    const float eps  = s_eps;
    const float tTile = t - 3.0f * eps - 1e-6f;
    const float tCand = t - 3.5f * eps - 1e-6f;
    __syncthreads();

    // qualifying tiles
    #pragma unroll
    for (int j = 0; j < 16; j++) {
        const int g = tid + TKT * j;
        if (tm[g] >= tTile) {
            int p = atomicAdd(&s_nt, 1);
            if (p < 2048) s_tiles[p] = g;
        }
    }
    __syncthreads();
    const int ntl = s_nt < 2048 ? s_nt : 2048;

    // candidates within qualifying tiles (bf16 screening values)
    const __nv_bfloat16* lg = g_logits + (size_t)row * ITEMS;
    const int wrp = tid >> 5, ln = tid & 31;
    for (int i = wrp; i < ntl; i += TKT / 32) {
        const int idx = s_tiles[i] * TM + ln;
        const float v = __bfloat162float(lg[idx]);
        if (v >= tCand) {
            int p = atomicAdd(&s_nc, 1);
            if (p < 2048) s_cidx[p] = idx;
        }
    }
    __syncthreads();
    const int C = s_nc < 2048 ? s_nc : 2048;

    // Rescore: ONE THREAD per candidate, sequential fmaf over k=0..127.
    // This is bit-identical to the round-1 fp32 GEMM accumulation order,
    // which matched the reference ranking exactly (rel_err 0.0).
    for (int i = tid; i < C; i += TKT) {
        const int idx = s_cidx[i];
        const float* wr = w + (size_t)idx * EMBED;
        float s = 0.0f;
        #pragma unroll
        for (int k4 = 0; k4 < EMBED / 4; k4++) {
            const float4 wv = ((const float4*)wr)[k4];
            s = fmaf(s_x[k4 * 4 + 0], wv.x, s);
            s = fmaf(s_x[k4 * 4 + 1], wv.y, s);
            s = fmaf(s_x[k4 * 4 + 2], wv.z, s);
            s = fmaf(s_x[k4 * 4 + 3], wv.w, s);
        }
        s_cand[i] = ((unsigned long long)fkey(s) << 32) |
                    (unsigned int)(~(unsigned int)idx);
    }
    __syncthreads();

    int P = 128;
    while (P < C) P <<= 1;
    for (int i = tid; i < P; i += TKT)
        if (i >= C) s_cand[i] = 0ULL;
    __syncthreads();

    for (int k = 2; k <= P; k <<= 1) {
        for (int j = k >> 1; j > 0; j >>= 1) {
            for (int i = tid; i < P; i += TKT) {
                const int ixj = i ^ j;
                if (ixj > i) {
                    const bool desc = ((i & k) == 0);
                    const unsigned long long a = s_cand[i], b = s_cand[ixj];
                    if (desc ? (a < b) : (a > b)) { s_cand[i] = b; s_cand[ixj] = a; }
                }
            }
            __syncthreads();
        }
    }

    if (tid < TOPK) {
        const unsigned int low = (unsigned int)s_cand[tid];
        out[(size_t)row * TOPK + tid] = (float)(~low);
    }
}

// ---------------------------------------------------------------------------
extern "C" void kernel_launch(void* const* d_in, const int* in_sizes, int n_in,
                              void* d_out, int out_size)
{
    const float* x = nullptr;
    const float* w = nullptr;
    for (int i = 0; i < n_in; i++) {
        if (in_sizes[i] == BATCH * EMBED)      x = (const float*)d_in[i];
        else if (in_sizes[i] == ITEMS * EMBED) w = (const float*)d_in[i];
    }
    float* out = (float*)d_out;

    static bool attr_set = false;
    if (!attr_set) {
        cudaFuncSetAttribute(gemm_screen,
                             cudaFuncAttributeMaxDynamicSharedMemorySize, 65536);
        attr_set = true;
    }

    dim3 grid(ITEMS / 128, BATCH / 128);
    gemm_screen<<<grid, 256, 65536>>>(x, w);
    topk_kernel<<<BATCH, TKT>>>(x, w, out);
}

// round 5
// speedup vs baseline: 2.7071x; 1.0407x over previous
#include <cuda_runtime.h>
#include <cuda_bf16.h>
#include <cstdint>

#define BATCH    1024
#define EMBED    128
#define ITEMS    262144
#define TOPK     100
#define TM       32               // tile-max granularity (items)
#define NTM      (ITEMS/TM)       // 8192 tile maxima per row

__device__ __nv_bfloat16 g_logits[(size_t)BATCH * ITEMS];
__device__ float         g_tilemax[(size_t)BATCH * NTM];

// ---------------------------------------------------------------------------
__device__ __forceinline__ uint32_t smem_u32(const void* p) {
    uint32_t a;
    asm("{ .reg .u64 t; cvta.to.shared.u64 t, %1; cvt.u32.u64 %0, t; }"
        : "=r"(a) : "l"(p));
    return a;
}
__device__ __forceinline__ uint32_t packbf(float lo, float hi) {
    uint32_t r;
    asm("cvt.rn.bf16x2.f32 %0, %1, %2;" : "=r"(r) : "f"(hi), "f"(lo));
    return r;
}

#define LDSM4(r0, r1, r2, r3, a)                                              \
    asm volatile("ldmatrix.sync.aligned.m8n8.x4.shared.b16 {%0,%1,%2,%3}, [%4];" \
        : "=r"(r0), "=r"(r1), "=r"(r2), "=r"(r3) : "r"(a))

#define MMA_BF16(d, A, b0, b1)                                                \
    asm volatile("mma.sync.aligned.m16n8k16.row.col.f32.bf16.bf16.f32 "       \
        "{%0,%1,%2,%3}, {%4,%5,%6,%7}, {%8,%9}, {%0,%1,%2,%3};"               \
        : "+f"((d)[0]), "+f"((d)[1]), "+f"((d)[2]), "+f"((d)[3])              \
        : "r"((A)[0]), "r"((A)[1]), "r"((A)[2]), "r"((A)[3]),                 \
          "r"(b0), "r"(b1))

// ---------------------------------------------------------------------------
// Screening GEMM: bf16 HMMA, CTA 256(M) x 128(N), K=128 single-shot in smem.
// 512 threads = 16 warps in 4(M) x 4(N); warp tile 64x32 = 4x4 m16n8k16.
// smem: A 64KB + B 32KB (bf16, 16B-chunk XOR swizzle).
// ---------------------------------------------------------------------------
#define GMB 256

__global__ __launch_bounds__(512, 1)
void gemm_screen(const float* __restrict__ x, const float* __restrict__ w)
{
    extern __shared__ char smem[];
    const uint32_t sb = smem_u32(smem);
    const int tid  = threadIdx.x;
    const int lane = tid & 31;
    const int wid  = tid >> 5;
    const int nBase   = blockIdx.x * 128;
    const int rowBase = blockIdx.y * GMB;

    // ---- Stage A (256x128) and B (128x128): fp32 -> bf16, swizzled ----
    const float4* x4 = (const float4*)(x + (size_t)rowBase * EMBED);
    const float4* w4 = (const float4*)(w + (size_t)nBase * EMBED);
    #pragma unroll
    for (int i = 0; i < 8; i++) {                 // A: 4096 16B-chunks
        const int flat = tid + 512 * i;
        const int r = flat >> 4, c = flat & 15;
        const int swc = c ^ (r & 7);
        float4 a0 = x4[flat * 2], a1 = x4[flat * 2 + 1];
        uint4 pa = make_uint4(packbf(a0.x, a0.y), packbf(a0.z, a0.w),
                              packbf(a1.x, a1.y), packbf(a1.z, a1.w));
        *(uint4*)(smem + r * 256 + swc * 16) = pa;
    }
    #pragma unroll
    for (int i = 0; i < 4; i++) {                 // B: 2048 16B-chunks
        const int flat = tid + 512 * i;
        const int r = flat >> 4, c = flat & 15;
        const int swc = c ^ (r & 7);
        float4 b0 = w4[flat * 2], b1 = w4[flat * 2 + 1];
        uint4 pb = make_uint4(packbf(b0.x, b0.y), packbf(b0.z, b0.w),
                              packbf(b1.x, b1.y), packbf(b1.z, b1.w));
        *(uint4*)(smem + 65536 + r * 256 + swc * 16) = pb;
    }
    __syncthreads();

    // ---- Compute ----
    const int wm = wid >> 2;          // 0..3
    const int wn = wid & 3;           // 0..3
    const int la7  = lane & 7;
    const int lg8  = (lane >> 3) & 1;
    const int cgrp = lane >> 4;

    int Aoff[4], Asw[4];
    #pragma unroll
    for (int a = 0; a < 4; a++) {
        const int rr = wm * 64 + a * 16 + la7 + lg8 * 8;
        Aoff[a] = rr * 256;  Asw[a] = rr & 7;
    }
    int Boff[2], Bsw[2];
    #pragma unroll
    for (int p = 0; p < 2; p++) {
        const int nr = wn * 32 + p * 16 + la7 + lg8 * 8;
        Boff[p] = 65536 + nr * 256;  Bsw[p] = nr & 7;
    }

    float d[4][4][4];
    #pragma unroll
    for (int a = 0; a < 4; a++)
        #pragma unroll
        for (int b = 0; b < 4; b++)
            #pragma unroll
            for (int q = 0; q < 4; q++) d[a][b][q] = 0.0f;

    #pragma unroll
    for (int ks = 0; ks < 8; ks++) {
        const int kc = ks * 2 + cgrp;
        uint32_t A[4][4], B[2][4];
        #pragma unroll
        for (int a = 0; a < 4; a++)
            LDSM4(A[a][0], A[a][1], A[a][2], A[a][3],
                  sb + Aoff[a] + ((kc ^ Asw[a]) << 4));
        #pragma unroll
        for (int p = 0; p < 2; p++)
            LDSM4(B[p][0], B[p][1], B[p][2], B[p][3],
                  sb + Boff[p] + ((kc ^ Bsw[p]) << 4));
        #pragma unroll
        for (int a = 0; a < 4; a++)
            #pragma unroll
            for (int b = 0; b < 4; b++)
                MMA_BF16(d[a][b], A[a], B[b >> 1][b & 1], B[b >> 1][(b & 1) + 2]);
    }

    // ---- Epilogue: bf16 logits + tile maxima ----
    const int colW = nBase + wn * 32;
    #pragma unroll
    for (int a = 0; a < 4; a++) {
        const int r1 = rowBase + wm * 64 + a * 16 + (lane >> 2);
        const int r2 = r1 + 8;
        float m1 = -3.402823466e+38f, m2 = m1;
        #pragma unroll
        for (int b = 0; b < 4; b++) {
            const int col = colW + b * 8 + 2 * (lane & 3);
            *(uint32_t*)((char*)g_logits + ((size_t)r1 * ITEMS + col) * 2) =
                packbf(d[a][b][0], d[a][b][1]);
            *(uint32_t*)((char*)g_logits + ((size_t)r2 * ITEMS + col) * 2) =
                packbf(d[a][b][2], d[a][b][3]);
            m1 = fmaxf(m1, fmaxf(d[a][b][0], d[a][b][1]));
            m2 = fmaxf(m2, fmaxf(d[a][b][2], d[a][b][3]));
        }
        m1 = fmaxf(m1, __shfl_xor_sync(0xFFFFFFFFu, m1, 1));
        m1 = fmaxf(m1, __shfl_xor_sync(0xFFFFFFFFu, m1, 2));
        m2 = fmaxf(m2, __shfl_xor_sync(0xFFFFFFFFu, m2, 1));
        m2 = fmaxf(m2, __shfl_xor_sync(0xFFFFFFFFu, m2, 2));
        if ((lane & 3) == 0) {
            const int grp = colW / TM;
            g_tilemax[(size_t)r1 * NTM + grp] = m1;
            g_tilemax[(size_t)r2 * NTM + grp] = m2;
        }
    }
}

// ---------------------------------------------------------------------------
// Top-k: 256 threads/CTA (occupancy!), threshold from 256 group maxima
// (1024 items each), candidate margins, exact sequential-fmaf rescore,
// bitonic sort of 64-bit keys.
// ---------------------------------------------------------------------------
#define TKT 256

__device__ __forceinline__ unsigned int fkey(float f) {
    unsigned int b = __float_as_uint(f);
    return b ^ ((b & 0x80000000u) ? 0xFFFFFFFFu : 0x80000000u);
}

__global__ __launch_bounds__(TKT)
void topk_kernel(const float* __restrict__ x, const float* __restrict__ w,
                 float* __restrict__ out)
{
    __shared__ float              s_x[EMBED];
    __shared__ float              s_max[TKT];
    __shared__ int                s_tiles[2048];
    __shared__ int                s_cidx[2048];
    __shared__ unsigned long long s_cand[2048];
    __shared__ int   s_nt, s_nc;
    __shared__ float s_eps;

    const int row = blockIdx.x;
    const int tid = threadIdx.x;
    const float* tm = g_tilemax + (size_t)row * NTM;

    if (tid < EMBED) s_x[tid] = x[(size_t)row * EMBED + tid];
    if (tid == 0) { s_nt = 0; s_nc = 0; }
    __syncthreads();

    // eps = 1.05 * 2^-7 * ||x||2 * (0.1*sqrt(128))
    if (tid < 32) {
        float ss = 0.0f;
        #pragma unroll
        for (int j = 0; j < 4; j++) { float v = s_x[tid * 4 + j]; ss += v * v; }
        #pragma unroll
        for (int o = 16; o > 0; o >>= 1) ss += __shfl_xor_sync(0xFFFFFFFFu, ss, o);
        if (tid == 0) s_eps = 1.05f * (1.0f / 128.0f) * sqrtf(ss) * 1.1313708f;
    }

    // group maxima: 32 tile-maxima per thread, coalesced strided
    float m = -3.402823466e+38f;
    #pragma unroll
    for (int j = 0; j < 32; j++) m = fmaxf(m, tm[tid + TKT * j]);
    s_max[tid] = m;
    __syncthreads();

    // bitonic sort 256 floats desc
    for (int k = 2; k <= TKT; k <<= 1) {
        for (int j = k >> 1; j > 0; j >>= 1) {
            const int ixj = tid ^ j;
            if (ixj > tid) {
                const bool desc = ((tid & k) == 0);
                const float a = s_max[tid], b = s_max[ixj];
                if (desc ? (a < b) : (a > b)) { s_max[tid] = b; s_max[ixj] = a; }
            }
            __syncthreads();
        }
    }
    const float t    = s_max[TOPK - 1];
    const float eps  = s_eps;
    const float tTile = t - 3.0f * eps - 1e-6f;
    const float tCand = t - 3.5f * eps - 1e-6f;
    __syncthreads();

    // qualifying tiles
    #pragma unroll
    for (int j = 0; j < 32; j++) {
        const int g = tid + TKT * j;
        if (tm[g] >= tTile) {
            int p = atomicAdd(&s_nt, 1);
            if (p < 2048) s_tiles[p] = g;
        }
    }
    __syncthreads();
    const int ntl = s_nt < 2048 ? s_nt : 2048;

    // candidates within qualifying tiles (bf16 screening values)
    const __nv_bfloat16* lg = g_logits + (size_t)row * ITEMS;
    const int wrp = tid >> 5, ln = tid & 31;
    for (int i = wrp; i < ntl; i += TKT / 32) {
        const int idx = s_tiles[i] * TM + ln;
        const float v = __bfloat162float(lg[idx]);
        if (v >= tCand) {
            int p = atomicAdd(&s_nc, 1);
            if (p < 2048) s_cidx[p] = idx;
        }
    }
    __syncthreads();
    const int C = s_nc < 2048 ? s_nc : 2048;

    // Rescore: ONE THREAD per candidate, sequential fmaf over k=0..127
    // (reference-matching accumulation order; bounded unroll to keep regs low)
    for (int i = tid; i < C; i += TKT) {
        const int idx = s_cidx[i];
        const float* wr = w + (size_t)idx * EMBED;
        float s = 0.0f;
        #pragma unroll 4
        for (int k4 = 0; k4 < EMBED / 4; k4++) {
            const float4 wv = ((const float4*)wr)[k4];
            s = fmaf(s_x[k4 * 4 + 0], wv.x, s);
            s = fmaf(s_x[k4 * 4 + 1], wv.y, s);
            s = fmaf(s_x[k4 * 4 + 2], wv.z, s);
            s = fmaf(s_x[k4 * 4 + 3], wv.w, s);
        }
        s_cand[i] = ((unsigned long long)fkey(s) << 32) |
                    (unsigned int)(~(unsigned int)idx);
    }
    __syncthreads();

    int P = 128;
    while (P < C) P <<= 1;
    for (int i = tid; i < P; i += TKT)
        if (i >= C) s_cand[i] = 0ULL;
    __syncthreads();

    for (int k = 2; k <= P; k <<= 1) {
        for (int j = k >> 1; j > 0; j >>= 1) {
            for (int i = tid; i < P; i += TKT) {
                const int ixj = i ^ j;
                if (ixj > i) {
                    const bool desc = ((i & k) == 0);
                    const unsigned long long a = s_cand[i], b = s_cand[ixj];
                    if (desc ? (a < b) : (a > b)) { s_cand[i] = b; s_cand[ixj] = a; }
                }
            }
            __syncthreads();
        }
    }

    if (tid < TOPK) {
        const unsigned int low = (unsigned int)s_cand[tid];
        out[(size_t)row * TOPK + tid] = (float)(~low);
    }
}

// ---------------------------------------------------------------------------
extern "C" void kernel_launch(void* const* d_in, const int* in_sizes, int n_in,
                              void* d_out, int out_size)
{
    const float* x = nullptr;
    const float* w = nullptr;
    for (int i = 0; i < n_in; i++) {
        if (in_sizes[i] == BATCH * EMBED)      x = (const float*)d_in[i];
        else if (in_sizes[i] == ITEMS * EMBED) w = (const float*)d_in[i];
    }
    float* out = (float*)d_out;

    static bool attr_set = false;
    if (!attr_set) {
        cudaFuncSetAttribute(gemm_screen,
                             cudaFuncAttributeMaxDynamicSharedMemorySize, 98304);
        attr_set = true;
    }

    dim3 grid(ITEMS / 128, BATCH / GMB);
    gemm_screen<<<grid, 512, 98304>>>(x, w);
    topk_kernel<<<BATCH, TKT>>>(x, w, out);
}

// round 6
// speedup vs baseline: 4.0613x; 1.5003x over previous
#include <cuda_runtime.h>
#include <cuda_bf16.h>
#include <cstdint>

#define BATCH    1024
#define EMBED    128
#define ITEMS    262144
#define TOPK     100
#define TM       32               // tile-max granularity (items)
#define NTM      (ITEMS/TM)       // 8192 tile maxima per row

#define NTILE    128              // items per GEMM N-tile
#define TPB      8                // N-tiles per CTA (pipelined loop)
#define GMB      256              // M rows per CTA

__device__ __nv_bfloat16 g_logits[(size_t)BATCH * ITEMS];
__device__ float         g_tilemax[(size_t)BATCH * NTM];

// ---------------------------------------------------------------------------
__device__ __forceinline__ uint32_t smem_u32(const void* p) {
    uint32_t a;
    asm("{ .reg .u64 t; cvta.to.shared.u64 t, %1; cvt.u32.u64 %0, t; }"
        : "=r"(a) : "l"(p));
    return a;
}
__device__ __forceinline__ uint32_t packbf(float lo, float hi) {
    uint32_t r;
    asm("cvt.rn.bf16x2.f32 %0, %1, %2;" : "=r"(r) : "f"(hi), "f"(lo));
    return r;
}

#define LDSM4(r0, r1, r2, r3, a)                                              \
    asm volatile("ldmatrix.sync.aligned.m8n8.x4.shared.b16 {%0,%1,%2,%3}, [%4];" \
        : "=r"(r0), "=r"(r1), "=r"(r2), "=r"(r3) : "r"(a))

#define MMA_BF16(d, A, b0, b1)                                                \
    asm volatile("mma.sync.aligned.m16n8k16.row.col.f32.bf16.bf16.f32 "       \
        "{%0,%1,%2,%3}, {%4,%5,%6,%7}, {%8,%9}, {%0,%1,%2,%3};"               \
        : "+f"((d)[0]), "+f"((d)[1]), "+f"((d)[2]), "+f"((d)[3])              \
        : "r"((A)[0]), "r"((A)[1]), "r"((A)[2]), "r"((A)[3]),                 \
          "r"(b0), "r"(b1))

// ---------------------------------------------------------------------------
// Pipelined screening GEMM: A panel 256x128 bf16 resident in smem; loop over
// 8 N-tiles of 128 items with double-buffered B and register prefetch.
// 512 threads = 16 warps (4M x 4N), warp tile 64x32.
// smem: A 64KB @0, B 2x32KB @65536.
// ---------------------------------------------------------------------------
__global__ __launch_bounds__(512, 1)
void gemm_screen(const float* __restrict__ x, const float* __restrict__ w)
{
    extern __shared__ char smem[];
    const uint32_t sb = smem_u32(smem);
    const int tid  = threadIdx.x;
    const int lane = tid & 31;
    const int wid  = tid >> 5;
    const int strip   = blockIdx.x;              // 256 strips of 1024 items
    const int rowBase = blockIdx.y * GMB;
    const int itemBase0 = strip * (NTILE * TPB);

    // ---- Stage A (256x128): fp32 -> bf16, 16B-chunk XOR swizzle ----
    const float4* x4 = (const float4*)(x + (size_t)rowBase * EMBED);
    #pragma unroll
    for (int i = 0; i < 8; i++) {                 // 4096 chunks
        const int flat = tid + 512 * i;
        const int r = flat >> 4, c = flat & 15;
        const int swc = c ^ (r & 7);
        float4 a0 = x4[flat * 2], a1 = x4[flat * 2 + 1];
        uint4 pa = make_uint4(packbf(a0.x, a0.y), packbf(a0.z, a0.w),
                              packbf(a1.x, a1.y), packbf(a1.z, a1.w));
        *(uint4*)(smem + r * 256 + swc * 16) = pa;
    }

    // B staging helpers: 2048 chunks per tile, 4 per thread
    const int br0 = tid >> 2;                     // chunk row for i=0 (flat=tid)
    // each thread's 4 chunks: flat = tid + 512*i -> r = flat>>4, c = flat&15

    // ---- Preload + stage tile 0 ----
    float4 pf[4][2];
    {
        const float4* wt = (const float4*)(w + (size_t)itemBase0 * EMBED);
        #pragma unroll
        for (int i = 0; i < 4; i++) {
            const int flat = tid + 512 * i;
            pf[i][0] = wt[flat * 2];
            pf[i][1] = wt[flat * 2 + 1];
        }
        #pragma unroll
        for (int i = 0; i < 4; i++) {
            const int flat = tid + 512 * i;
            const int r = flat >> 4, c = flat & 15;
            const int swc = c ^ (r & 7);
            uint4 pb = make_uint4(packbf(pf[i][0].x, pf[i][0].y),
                                  packbf(pf[i][0].z, pf[i][0].w),
                                  packbf(pf[i][1].x, pf[i][1].y),
                                  packbf(pf[i][1].z, pf[i][1].w));
            *(uint4*)(smem + 65536 + r * 256 + swc * 16) = pb;
        }
    }
    __syncthreads();

    // ---- fragment addressing ----
    const int wm = wid >> 2;          // 0..3
    const int wn = wid & 3;           // 0..3
    const int la7  = lane & 7;
    const int lg8  = (lane >> 3) & 1;
    const int cgrp = lane >> 4;

    int Aoff[4], Asw[4];
    #pragma unroll
    for (int a = 0; a < 4; a++) {
        const int rr = wm * 64 + a * 16 + la7 + lg8 * 8;
        Aoff[a] = rr * 256;  Asw[a] = rr & 7;
    }
    int BoffR[2], Bsw[2];
    #pragma unroll
    for (int p = 0; p < 2; p++) {
        const int nr = wn * 32 + p * 16 + la7 + lg8 * 8;
        BoffR[p] = nr * 256;  Bsw[p] = nr & 7;
    }

    // ---- Pipelined tile loop ----
    for (int n = 0; n < TPB; n++) {
        const int cur = n & 1;
        const int itemBase = itemBase0 + n * NTILE;

        // prefetch next tile into regs (overlaps with MMA below)
        if (n + 1 < TPB) {
            const float4* wt = (const float4*)(w + (size_t)(itemBase + NTILE) * EMBED);
            #pragma unroll
            for (int i = 0; i < 4; i++) {
                const int flat = tid + 512 * i;
                pf[i][0] = wt[flat * 2];
                pf[i][1] = wt[flat * 2 + 1];
            }
        }

        // MMA on buffer cur
        float d[4][4][4];
        #pragma unroll
        for (int a = 0; a < 4; a++)
            #pragma unroll
            for (int b = 0; b < 4; b++)
                #pragma unroll
                for (int q = 0; q < 4; q++) d[a][b][q] = 0.0f;

        const uint32_t bBase = sb + 65536 + cur * 32768;
        #pragma unroll
        for (int ks = 0; ks < 8; ks++) {
            const int kc = ks * 2 + cgrp;
            uint32_t A[4][4], B[2][4];
            #pragma unroll
            for (int a = 0; a < 4; a++)
                LDSM4(A[a][0], A[a][1], A[a][2], A[a][3],
                      sb + Aoff[a] + ((kc ^ Asw[a]) << 4));
            #pragma unroll
            for (int p = 0; p < 2; p++)
                LDSM4(B[p][0], B[p][1], B[p][2], B[p][3],
                      bBase + BoffR[p] + ((kc ^ Bsw[p]) << 4));
            #pragma unroll
            for (int a = 0; a < 4; a++)
                #pragma unroll
                for (int b = 0; b < 4; b++)
                    MMA_BF16(d[a][b], A[a], B[b >> 1][b & 1], B[b >> 1][(b & 1) + 2]);
        }

        // stage next tile into the other buffer
        if (n + 1 < TPB) {
            char* bnext = smem + 65536 + (cur ^ 1) * 32768;
            #pragma unroll
            for (int i = 0; i < 4; i++) {
                const int flat = tid + 512 * i;
                const int r = flat >> 4, c = flat & 15;
                const int swc = c ^ (r & 7);
                uint4 pb = make_uint4(packbf(pf[i][0].x, pf[i][0].y),
                                      packbf(pf[i][0].z, pf[i][0].w),
                                      packbf(pf[i][1].x, pf[i][1].y),
                                      packbf(pf[i][1].z, pf[i][1].w));
                *(uint4*)(bnext + r * 256 + swc * 16) = pb;
            }
        }

        // epilogue: bf16 logits + tile maxima
        const int colW = itemBase + wn * 32;
        #pragma unroll
        for (int a = 0; a < 4; a++) {
            const int r1 = rowBase + wm * 64 + a * 16 + (lane >> 2);
            const int r2 = r1 + 8;
            float m1 = -3.402823466e+38f, m2 = m1;
            #pragma unroll
            for (int b = 0; b < 4; b++) {
                const int col = colW + b * 8 + 2 * (lane & 3);
                *(uint32_t*)((char*)g_logits + ((size_t)r1 * ITEMS + col) * 2) =
                    packbf(d[a][b][0], d[a][b][1]);
                *(uint32_t*)((char*)g_logits + ((size_t)r2 * ITEMS + col) * 2) =
                    packbf(d[a][b][2], d[a][b][3]);
                m1 = fmaxf(m1, fmaxf(d[a][b][0], d[a][b][1]));
                m2 = fmaxf(m2, fmaxf(d[a][b][2], d[a][b][3]));
            }
            m1 = fmaxf(m1, __shfl_xor_sync(0xFFFFFFFFu, m1, 1));
            m1 = fmaxf(m1, __shfl_xor_sync(0xFFFFFFFFu, m1, 2));
            m2 = fmaxf(m2, __shfl_xor_sync(0xFFFFFFFFu, m2, 1));
            m2 = fmaxf(m2, __shfl_xor_sync(0xFFFFFFFFu, m2, 2));
            if ((lane & 3) == 0) {
                const int grp = colW / TM;
                g_tilemax[(size_t)r1 * NTM + grp] = m1;
                g_tilemax[(size_t)r2 * NTM + grp] = m2;
            }
        }

        if (n + 1 < TPB) __syncthreads();
    }
}

// ---------------------------------------------------------------------------
// Top-k. Margin math (rigorous): per-item screen error bound
//   B = 2^-8 * ||x||2 * max||w||2 <= 2^-8 * ||x||2 * 0.1*sqrt(128).
// eps below = 2.1*B. Guarantee chain: >=100 screen values >= t (group maxima
// are distinct items) -> exact 100th value >= t - B -> every true top-100
// item has screen value >= t - 2B. margin 1.05*eps = 2.2*B > 2B. 
// ---------------------------------------------------------------------------
#define TKT  256
#define CMAX 1024

__device__ __forceinline__ unsigned int fkey(float f) {
    unsigned int b = __float_as_uint(f);
    return b ^ ((b & 0x80000000u) ? 0xFFFFFFFFu : 0x80000000u);
}

// warp-aggregated append: returns slot for this thread (pred true lanes only)
__device__ __forceinline__ int wagg_append(int* ctr, bool pred, int ln) {
    const unsigned mask = __ballot_sync(0xFFFFFFFFu, pred);
    if (!pred) return -1;
    const int leader = __ffs(mask) - 1;
    int base = 0;
    if (ln == leader) base = atomicAdd(ctr, __popc(mask));
    base = __shfl_sync(mask, base, leader);
    return base + __popc(mask & ((1u << ln) - 1u));
}

__global__ __launch_bounds__(TKT)
void topk_kernel(const float* __restrict__ x, const float* __restrict__ w,
                 float* __restrict__ out)
{
    __shared__ float              s_x[EMBED];
    __shared__ float              s_max[TKT];
    __shared__ int                s_tiles[CMAX];
    __shared__ int                s_cidx[CMAX];
    __shared__ unsigned long long s_cand[CMAX];
    __shared__ int   s_nt, s_nc;
    __shared__ float s_eps;

    const int row = blockIdx.x;
    const int tid = threadIdx.x;
    const int wrp = tid >> 5, ln = tid & 31;
    const float* tm = g_tilemax + (size_t)row * NTM;

    if (tid < EMBED) s_x[tid] = x[(size_t)row * EMBED + tid];
    if (tid == 0) { s_nt = 0; s_nc = 0; }
    __syncthreads();

    // eps = 1.05 * 2^-7 * ||x||2 * 0.1*sqrt(128)   (= 2.1x true bound)
    if (tid < 32) {
        float ss = 0.0f;
        #pragma unroll
        for (int j = 0; j < 4; j++) { float v = s_x[tid * 4 + j]; ss += v * v; }
        #pragma unroll
        for (int o = 16; o > 0; o >>= 1) ss += __shfl_xor_sync(0xFFFFFFFFu, ss, o);
        if (tid == 0) s_eps = 1.05f * (1.0f / 128.0f) * sqrtf(ss) * 1.1313708f;
    }

    // group maxima: 32 tile-maxima per thread, coalesced strided
    float m = -3.402823466e+38f;
    #pragma unroll
    for (int j = 0; j < 32; j++) m = fmaxf(m, tm[tid + TKT * j]);
    s_max[tid] = m;
    __syncthreads();

    // bitonic sort 256 floats desc
    for (int k = 2; k <= TKT; k <<= 1) {
        for (int j = k >> 1; j > 0; j >>= 1) {
            const int ixj = tid ^ j;
            if (ixj > tid) {
                const bool desc = ((tid & k) == 0);
                const float a = s_max[tid], b = s_max[ixj];
                if (desc ? (a < b) : (a > b)) { s_max[tid] = b; s_max[ixj] = a; }
            }
            __syncthreads();
        }
    }
    const float thr = s_max[TOPK - 1] - 1.05f * s_eps - 1e-5f;
    __syncthreads();

    // qualifying tiles (warp-aggregated append)
    #pragma unroll
    for (int j = 0; j < 32; j++) {
        const int g = tid + TKT * j;
        const bool q = (tm[g] >= thr);
        const int p = wagg_append(&s_nt, q, ln);
        if (q && p < CMAX) s_tiles[p] = g;
    }
    __syncthreads();
    const int ntl = s_nt < CMAX ? s_nt : CMAX;

    // candidates within qualifying tiles
    const __nv_bfloat16* lg = g_logits + (size_t)row * ITEMS;
    for (int i = wrp; i < ntl; i += TKT / 32) {
        const int idx = s_tiles[i] * TM + ln;
        const float v = __bfloat162float(lg[idx]);
        const bool q = (v >= thr);
        const int p = wagg_append(&s_nc, q, ln);
        if (q && p < CMAX) s_cidx[p] = idx;
    }
    __syncthreads();
    const int C = s_nc < CMAX ? s_nc : CMAX;

    // Rescore: ONE THREAD per candidate, sequential fmaf over k=0..127
    // (reference-matching accumulation order)
    for (int i = tid; i < C; i += TKT) {
        const int idx = s_cidx[i];
        const float* wr = w + (size_t)idx * EMBED;
        float s = 0.0f;
        #pragma unroll 8
        for (int k4 = 0; k4 < EMBED / 4; k4++) {
            const float4 wv = ((const float4*)wr)[k4];
            s = fmaf(s_x[k4 * 4 + 0], wv.x, s);
            s = fmaf(s_x[k4 * 4 + 1], wv.y, s);
            s = fmaf(s_x[k4 * 4 + 2], wv.z, s);
            s = fmaf(s_x[k4 * 4 + 3], wv.w, s);
        }
        s_cand[i] = ((unsigned long long)fkey(s) << 32) |
                    (unsigned int)(~(unsigned int)idx);
    }
    __syncthreads();

    int P = 128;
    while (P < C) P <<= 1;
    for (int i = tid; i < P; i += TKT)
        if (i >= C) s_cand[i] = 0ULL;
    __syncthreads();

    // bitonic sort P 64-bit keys desc (value desc, index asc on ties)
    for (int k = 2; k <= P; k <<= 1) {
        for (int j = k >> 1; j > 0; j >>= 1) {
            for (int i = tid; i < P; i += TKT) {
                const int ixj = i ^ j;
                if (ixj > i) {
                    const bool desc = ((i & k) == 0);
                    const unsigned long long a = s_cand[i], b = s_cand[ixj];
                    if (desc ? (a < b) : (a > b)) { s_cand[i] = b; s_cand[ixj] = a; }
                }
            }
            __syncthreads();
        }
    }

    if (tid < TOPK) {
        const unsigned int low = (unsigned int)s_cand[tid];
        out[(size_t)row * TOPK + tid] = (float)(~low);
    }
}

// ---------------------------------------------------------------------------
extern "C" void kernel_launch(void* const* d_in, const int* in_sizes, int n_in,
                              void* d_out, int out_size)
{
    const float* x = nullptr;
    const float* w = nullptr;
    for (int i = 0; i < n_in; i++) {
        if (in_sizes[i] == BATCH * EMBED)      x = (const float*)d_in[i];
        else if (in_sizes[i] == ITEMS * EMBED) w = (const float*)d_in[i];
    }
    float* out = (float*)d_out;

    static bool attr_set = false;
    if (!attr_set) {
        cudaFuncSetAttribute(gemm_screen,
                             cudaFuncAttributeMaxDynamicSharedMemorySize, 131072);
        attr_set = true;
    }

    dim3 grid(ITEMS / (NTILE * TPB), BATCH / GMB);   // (256, 4)
    gemm_screen<<<grid, 512, 131072>>>(x, w);
    topk_kernel<<<BATCH, TKT>>>(x, w, out);
}

// round 7
// speedup vs baseline: 4.2738x; 1.0523x over previous
#include <cuda_runtime.h>
#include <cuda_bf16.h>
#include <cstdint>

#define BATCH    1024
#define EMBED    128
#define ITEMS    262144
#define TOPK     100
#define TM       32               // tile-max granularity (items)
#define NTM      (ITEMS/TM)       // 8192 tile maxima per row

#define NTILE    128              // items per GEMM N-tile
#define TPB      8                // N-tiles per CTA (pipelined loop)
#define GMB      256              // M rows per CTA

__device__ __nv_bfloat16 g_logits[(size_t)BATCH * ITEMS];
__device__ float         g_tilemax[(size_t)BATCH * NTM];

// ---------------------------------------------------------------------------
__device__ __forceinline__ uint32_t smem_u32(const void* p) {
    uint32_t a;
    asm("{ .reg .u64 t; cvta.to.shared.u64 t, %1; cvt.u32.u64 %0, t; }"
        : "=r"(a) : "l"(p));
    return a;
}
__device__ __forceinline__ uint32_t packbf(float lo, float hi) {
    uint32_t r;
    asm("cvt.rn.bf16x2.f32 %0, %1, %2;" : "=r"(r) : "f"(hi), "f"(lo));
    return r;
}

#define LDSM4(r0, r1, r2, r3, a)                                              \
    asm volatile("ldmatrix.sync.aligned.m8n8.x4.shared.b16 {%0,%1,%2,%3}, [%4];" \
        : "=r"(r0), "=r"(r1), "=r"(r2), "=r"(r3) : "r"(a))

#define STSM4(a, r0, r1, r2, r3)                                              \
    asm volatile("stmatrix.sync.aligned.m8n8.x4.shared.b16 [%0], {%1,%2,%3,%4};" \
        :: "r"(a), "r"(r0), "r"(r1), "r"(r2), "r"(r3) : "memory")

#define MMA_BF16(d, A, b0, b1)                                                \
    asm volatile("mma.sync.aligned.m16n8k16.row.col.f32.bf16.bf16.f32 "       \
        "{%0,%1,%2,%3}, {%4,%5,%6,%7}, {%8,%9}, {%0,%1,%2,%3};"               \
        : "+f"((d)[0]), "+f"((d)[1]), "+f"((d)[2]), "+f"((d)[3])              \
        : "r"((A)[0]), "r"((A)[1]), "r"((A)[2]), "r"((A)[3]),                 \
          "r"(b0), "r"(b1))

// ---------------------------------------------------------------------------
// Pipelined screening GEMM: A panel 256x128 bf16 resident; 8 N-tiles of 128
// items, double-buffered B, register prefetch. Epilogue via stmatrix into a
// swizzled smem stage, then fully-coalesced uint4 stores.
// smem: A 64KB @0, B 2x32KB @65536, STAGE 64KB @131072 (192KB total).
// ---------------------------------------------------------------------------
#define SM_B     65536
#define SM_STAGE 131072
#define SM_TOTAL 196608

__global__ __launch_bounds__(512, 1)
void gemm_screen(const float* __restrict__ x, const float* __restrict__ w)
{
    extern __shared__ char smem[];
    const uint32_t sb = smem_u32(smem);
    const int tid  = threadIdx.x;
    const int lane = tid & 31;
    const int wid  = tid >> 5;
    const int strip   = blockIdx.x;
    const int rowBase = blockIdx.y * GMB;
    const int itemBase0 = strip * (NTILE * TPB);

    // ---- Stage A (256x128): fp32 -> bf16, 16B-chunk XOR swizzle ----
    const float4* x4 = (const float4*)(x + (size_t)rowBase * EMBED);
    #pragma unroll
    for (int i = 0; i < 8; i++) {
        const int flat = tid + 512 * i;
        const int r = flat >> 4, c = flat & 15;
        const int swc = c ^ (r & 7);
        float4 a0 = x4[flat * 2], a1 = x4[flat * 2 + 1];
        uint4 pa = make_uint4(packbf(a0.x, a0.y), packbf(a0.z, a0.w),
                              packbf(a1.x, a1.y), packbf(a1.z, a1.w));
        *(uint4*)(smem + r * 256 + swc * 16) = pa;
    }

    // ---- Preload + stage B tile 0 ----
    float4 pf[4][2];
    {
        const float4* wt = (const float4*)(w + (size_t)itemBase0 * EMBED);
        #pragma unroll
        for (int i = 0; i < 4; i++) {
            const int flat = tid + 512 * i;
            pf[i][0] = wt[flat * 2];
            pf[i][1] = wt[flat * 2 + 1];
        }
        #pragma unroll
        for (int i = 0; i < 4; i++) {
            const int flat = tid + 512 * i;
            const int r = flat >> 4, c = flat & 15;
            const int swc = c ^ (r & 7);
            uint4 pb = make_uint4(packbf(pf[i][0].x, pf[i][0].y),
                                  packbf(pf[i][0].z, pf[i][0].w),
                                  packbf(pf[i][1].x, pf[i][1].y),
                                  packbf(pf[i][1].z, pf[i][1].w));
            *(uint4*)(smem + SM_B + r * 256 + swc * 16) = pb;
        }
    }
    __syncthreads();

    // ---- fragment addressing ----
    const int wm = wid >> 2;          // 0..3
    const int wn = wid & 3;           // 0..3
    const int la7  = lane & 7;
    const int lg8  = (lane >> 3) & 1;
    const int cgrp = lane >> 4;

    int Aoff[4], Asw[4];
    #pragma unroll
    for (int a = 0; a < 4; a++) {
        const int rr = wm * 64 + a * 16 + la7 + lg8 * 8;
        Aoff[a] = rr * 256;  Asw[a] = rr & 7;
    }
    int BoffR[2], Bsw[2];
    #pragma unroll
    for (int p = 0; p < 2; p++) {
        const int nr = wn * 32 + p * 16 + la7 + lg8 * 8;
        BoffR[p] = nr * 256;  Bsw[p] = nr & 7;
    }

    // stmatrix addressing: row within 64-row warp block (before +a*16),
    // chunk (16B col unit) before +bp*2
    const int smRow0    = wm * 64 + lg8 * 8 + la7;     // lanes 0-15 pattern
    const int chunk0    = wn * 4 + (lane >> 4);        // lanes>=16 -> col +8

    // ---- Pipelined tile loop ----
    for (int n = 0; n < TPB; n++) {
        const int cur = n & 1;
        const int itemBase = itemBase0 + n * NTILE;

        // prefetch next tile into regs (overlaps with MMA)
        if (n + 1 < TPB) {
            const float4* wt = (const float4*)(w + (size_t)(itemBase + NTILE) * EMBED);
            #pragma unroll
            for (int i = 0; i < 4; i++) {
                const int flat = tid + 512 * i;
                pf[i][0] = wt[flat * 2];
                pf[i][1] = wt[flat * 2 + 1];
            }
        }

        // MMA on buffer cur
        float d[4][4][4];
        #pragma unroll
        for (int a = 0; a < 4; a++)
            #pragma unroll
            for (int b = 0; b < 4; b++)
                #pragma unroll
                for (int q = 0; q < 4; q++) d[a][b][q] = 0.0f;

        const uint32_t bBase = sb + SM_B + cur * 32768;
        #pragma unroll
        for (int ks = 0; ks < 8; ks++) {
            const int kc = ks * 2 + cgrp;
            uint32_t A[4][4], B[2][4];
            #pragma unroll
            for (int a = 0; a < 4; a++)
                LDSM4(A[a][0], A[a][1], A[a][2], A[a][3],
                      sb + Aoff[a] + ((kc ^ Asw[a]) << 4));
            #pragma unroll
            for (int p = 0; p < 2; p++)
                LDSM4(B[p][0], B[p][1], B[p][2], B[p][3],
                      bBase + BoffR[p] + ((kc ^ Bsw[p]) << 4));
            #pragma unroll
            for (int a = 0; a < 4; a++)
                #pragma unroll
                for (int b = 0; b < 4; b++)
                    MMA_BF16(d[a][b], A[a], B[b >> 1][b & 1], B[b >> 1][(b & 1) + 2]);
        }

        // stage next B tile into the other buffer
        if (n + 1 < TPB) {
            char* bnext = smem + SM_B + (cur ^ 1) * 32768;
            #pragma unroll
            for (int i = 0; i < 4; i++) {
                const int flat = tid + 512 * i;
                const int r = flat >> 4, c = flat & 15;
                const int swc = c ^ (r & 7);
                uint4 pb = make_uint4(packbf(pf[i][0].x, pf[i][0].y),
                                      packbf(pf[i][0].z, pf[i][0].w),
                                      packbf(pf[i][1].x, pf[i][1].y),
                                      packbf(pf[i][1].z, pf[i][1].w));
                *(uint4*)(bnext + r * 256 + swc * 16) = pb;
            }
        }

        // ---- Epilogue part 1: pack, tilemax, stmatrix into swizzled stage
        const int colW = itemBase + wn * 32;
        #pragma unroll
        for (int a = 0; a < 4; a++) {
            uint32_t p[8];
            float m1 = -3.402823466e+38f, m2 = m1;
            #pragma unroll
            for (int b = 0; b < 4; b++) {
                p[b * 2 + 0] = packbf(d[a][b][0], d[a][b][1]);
                p[b * 2 + 1] = packbf(d[a][b][2], d[a][b][3]);
                m1 = fmaxf(m1, fmaxf(d[a][b][0], d[a][b][1]));
                m2 = fmaxf(m2, fmaxf(d[a][b][2], d[a][b][3]));
            }
            const int row = smRow0 + a * 16;
            #pragma unroll
            for (int bp = 0; bp < 2; bp++) {
                const int ch = chunk0 + bp * 2;
                const uint32_t addr = sb + SM_STAGE + row * 256
                                    + ((ch ^ (row & 7)) << 4);
                STSM4(addr, p[bp * 4 + 0], p[bp * 4 + 1],
                            p[bp * 4 + 2], p[bp * 4 + 3]);
            }
            // tile maxima (row owned by lane>>2 within atom, cols via shfl)
            m1 = fmaxf(m1, __shfl_xor_sync(0xFFFFFFFFu, m1, 1));
            m1 = fmaxf(m1, __shfl_xor_sync(0xFFFFFFFFu, m1, 2));
            m2 = fmaxf(m2, __shfl_xor_sync(0xFFFFFFFFu, m2, 1));
            m2 = fmaxf(m2, __shfl_xor_sync(0xFFFFFFFFu, m2, 2));
            if ((lane & 3) == 0) {
                const int r1 = rowBase + wm * 64 + a * 16 + (lane >> 2);
                const int grp = colW / TM;
                g_tilemax[(size_t)r1 * NTM + grp]       = m1;
                g_tilemax[(size_t)(r1 + 8) * NTM + grp] = m2;
            }
        }
        __syncthreads();

        // ---- Epilogue part 2: coalesced copy-out (256 rows x 256B) ----
        #pragma unroll
        for (int i = 0; i < 8; i++) {
            const int flat = tid + 512 * i;
            const int r = flat >> 4, c = flat & 15;
            const uint4 v = *(const uint4*)(smem + SM_STAGE + r * 256
                                            + ((c ^ (r & 7)) << 4));
            *(uint4*)((char*)g_logits
                      + ((size_t)(rowBase + r) * ITEMS + itemBase) * 2
                      + c * 16) = v;
        }

        if (n + 1 < TPB) __syncthreads();
    }
}

// ---------------------------------------------------------------------------
// Top-k (unchanged from round 6; 120us, proven exact).
// ---------------------------------------------------------------------------
#define TKT  256
#define CMAX 1024

__device__ __forceinline__ unsigned int fkey(float f) {
    unsigned int b = __float_as_uint(f);
    return b ^ ((b & 0x80000000u) ? 0xFFFFFFFFu : 0x80000000u);
}

__device__ __forceinline__ int wagg_append(int* ctr, bool pred, int ln) {
    const unsigned mask = __ballot_sync(0xFFFFFFFFu, pred);
    if (!pred) return -1;
    const int leader = __ffs(mask) - 1;
    int base = 0;
    if (ln == leader) base = atomicAdd(ctr, __popc(mask));
    base = __shfl_sync(mask, base, leader);
    return base + __popc(mask & ((1u << ln) - 1u));
}

__global__ __launch_bounds__(TKT)
void topk_kernel(const float* __restrict__ x, const float* __restrict__ w,
                 float* __restrict__ out)
{
    __shared__ float              s_x[EMBED];
    __shared__ float              s_max[TKT];
    __shared__ int                s_tiles[CMAX];
    __shared__ int                s_cidx[CMAX];
    __shared__ unsigned long long s_cand[CMAX];
    __shared__ int   s_nt, s_nc;
    __shared__ float s_eps;

    const int row = blockIdx.x;
    const int tid = threadIdx.x;
    const int wrp = tid >> 5, ln = tid & 31;
    const float* tm = g_tilemax + (size_t)row * NTM;

    if (tid < EMBED) s_x[tid] = x[(size_t)row * EMBED + tid];
    if (tid == 0) { s_nt = 0; s_nc = 0; }
    __syncthreads();

    if (tid < 32) {
        float ss = 0.0f;
        #pragma unroll
        for (int j = 0; j < 4; j++) { float v = s_x[tid * 4 + j]; ss += v * v; }
        #pragma unroll
        for (int o = 16; o > 0; o >>= 1) ss += __shfl_xor_sync(0xFFFFFFFFu, ss, o);
        if (tid == 0) s_eps = 1.05f * (1.0f / 128.0f) * sqrtf(ss) * 1.1313708f;
    }

    float m = -3.402823466e+38f;
    #pragma unroll
    for (int j = 0; j < 32; j++) m = fmaxf(m, tm[tid + TKT * j]);
    s_max[tid] = m;
    __syncthreads();

    for (int k = 2; k <= TKT; k <<= 1) {
        for (int j = k >> 1; j > 0; j >>= 1) {
            const int ixj = tid ^ j;
            if (ixj > tid) {
                const bool desc = ((tid & k) == 0);
                const float a = s_max[tid], b = s_max[ixj];
                if (desc ? (a < b) : (a > b)) { s_max[tid] = b; s_max[ixj] = a; }
            }
            __syncthreads();
        }
    }
    const float thr = s_max[TOPK - 1] - 1.05f * s_eps - 1e-5f;
    __syncthreads();

    #pragma unroll
    for (int j = 0; j < 32; j++) {
        const int g = tid + TKT * j;
        const bool q = (tm[g] >= thr);
        const int p = wagg_append(&s_nt, q, ln);
        if (q && p < CMAX) s_tiles[p] = g;
    }
    __syncthreads();
    const int ntl = s_nt < CMAX ? s_nt : CMAX;

    const __nv_bfloat16* lg = g_logits + (size_t)row * ITEMS;
    for (int i = wrp; i < ntl; i += TKT / 32) {
        const int idx = s_tiles[i] * TM + ln;
        const float v = __bfloat162float(lg[idx]);
        const bool q = (v >= thr);
        const int p = wagg_append(&s_nc, q, ln);
        if (q && p < CMAX) s_cidx[p] = idx;
    }
    __syncthreads();
    const int C = s_nc < CMAX ? s_nc : CMAX;

    for (int i = tid; i < C; i += TKT) {
        const int idx = s_cidx[i];
        const float* wr = w + (size_t)idx * EMBED;
        float s = 0.0f;
        #pragma unroll 8
        for (int k4 = 0; k4 < EMBED / 4; k4++) {
            const float4 wv = ((const float4*)wr)[k4];
            s = fmaf(s_x[k4 * 4 + 0], wv.x, s);
            s = fmaf(s_x[k4 * 4 + 1], wv.y, s);
            s = fmaf(s_x[k4 * 4 + 2], wv.z, s);
            s = fmaf(s_x[k4 * 4 + 3], wv.w, s);
        }
        s_cand[i] = ((unsigned long long)fkey(s) << 32) |
                    (unsigned int)(~(unsigned int)idx);
    }
    __syncthreads();

    int P = 128;
    while (P < C) P <<= 1;
    for (int i = tid; i < P; i += TKT)
        if (i >= C) s_cand[i] = 0ULL;
    __syncthreads();

    for (int k = 2; k <= P; k <<= 1) {
        for (int j = k >> 1; j > 0; j >>= 1) {
            for (int i = tid; i < P; i += TKT) {
                const int ixj = i ^ j;
                if (ixj > i) {
                    const bool desc = ((i & k) == 0);
                    const unsigned long long a = s_cand[i], b = s_cand[ixj];
                    if (desc ? (a < b) : (a > b)) { s_cand[i] = b; s_cand[ixj] = a; }
                }
            }
            __syncthreads();
        }
    }

    if (tid < TOPK) {
        const unsigned int low = (unsigned int)s_cand[tid];
        out[(size_t)row * TOPK + tid] = (float)(~low);
    }
}

// ---------------------------------------------------------------------------
extern "C" void kernel_launch(void* const* d_in, const int* in_sizes, int n_in,
                              void* d_out, int out_size)
{
    const float* x = nullptr;
    const float* w = nullptr;
    for (int i = 0; i < n_in; i++) {
        if (in_sizes[i] == BATCH * EMBED)      x = (const float*)d_in[i];
        else if (in_sizes[i] == ITEMS * EMBED) w = (const float*)d_in[i];
    }
    float* out = (float*)d_out;

    static bool attr_set = false;
    if (!attr_set) {
        cudaFuncSetAttribute(gemm_screen,
                             cudaFuncAttributeMaxDynamicSharedMemorySize, SM_TOTAL);
        attr_set = true;
    }

    dim3 grid(ITEMS / (NTILE * TPB), BATCH / GMB);   // (256, 4)
    gemm_screen<<<grid, 512, SM_TOTAL>>>(x, w);
    topk_kernel<<<BATCH, TKT>>>(x, w, out);
}

// round 8
// speedup vs baseline: 4.7569x; 1.1130x over previous
#include <cuda_runtime.h>
#include <cuda_bf16.h>
#include <cstdint>

#define BATCH    1024
#define EMBED    128
#define ITEMS    262144
#define TOPK     100
#define TM       32               // tile-max granularity (items)
#define NTM      (ITEMS/TM)       // 8192 tile maxima per row

#define NTILE    64               // items per GEMM N-tile
#define TPB      16               // N-tiles per CTA
#define GMB      128              // M rows per CTA

__device__ __nv_bfloat16 g_logits[(size_t)BATCH * ITEMS];
__device__ float         g_tilemax[(size_t)BATCH * NTM];

// ---------------------------------------------------------------------------
__device__ __forceinline__ uint32_t smem_u32(const void* p) {
    uint32_t a;
    asm("{ .reg .u64 t; cvta.to.shared.u64 t, %1; cvt.u32.u64 %0, t; }"
        : "=r"(a) : "l"(p));
    return a;
}
__device__ __forceinline__ uint32_t packbf(float lo, float hi) {
    uint32_t r;
    asm("cvt.rn.bf16x2.f32 %0, %1, %2;" : "=r"(r) : "f"(hi), "f"(lo));
    return r;
}

#define LDSM4(r0, r1, r2, r3, a)                                              \
    asm volatile("ldmatrix.sync.aligned.m8n8.x4.shared.b16 {%0,%1,%2,%3}, [%4];" \
        : "=r"(r0), "=r"(r1), "=r"(r2), "=r"(r3) : "r"(a))

#define STSM4(a, r0, r1, r2, r3)                                              \
    asm volatile("stmatrix.sync.aligned.m8n8.x4.shared.b16 [%0], {%1,%2,%3,%4};" \
        :: "r"(a), "r"(r0), "r"(r1), "r"(r2), "r"(r3) : "memory")

#define MMA_BF16(d, A, b0, b1)                                                \
    asm volatile("mma.sync.aligned.m16n8k16.row.col.f32.bf16.bf16.f32 "       \
        "{%0,%1,%2,%3}, {%4,%5,%6,%7}, {%8,%9}, {%0,%1,%2,%3};"               \
        : "+f"((d)[0]), "+f"((d)[1]), "+f"((d)[2]), "+f"((d)[3])              \
        : "r"((A)[0]), "r"((A)[1]), "r"((A)[2]), "r"((A)[3]),                 \
          "r"(b0), "r"(b1))

// ---------------------------------------------------------------------------
// Screening GEMM, 2 CTAs/SM version.
// CTA: 128(M) x 64(N-tile) x 16 tiles, 256 threads = 8 warps (4M x 2N),
// warp tile 32x32. A resident 32KB; B double-buffered 2x16KB; epilogue
// stage double-buffered 2x16KB -> ONE sync per tile, copy-out lags one tile.
// Grid (panel=8, strip=256): CTAs sharing a w strip are launch-adjacent -> L2 reuse.
// ---------------------------------------------------------------------------
#define SM_B      32768
#define SM_STAGE  65536
#define BTILE_SZ  16384
#define STAGE_SZ  16384
#define SM_TOTAL  98304

__global__ __launch_bounds__(256, 2)
void gemm_screen(const float* __restrict__ x, const float* __restrict__ w)
{
    extern __shared__ char smem[];
    const uint32_t sb = smem_u32(smem);
    const int tid  = threadIdx.x;
    const int lane = tid & 31;
    const int wid  = tid >> 5;
    const int rowBase   = blockIdx.x * GMB;          // panel (fast dim)
    const int itemBase0 = blockIdx.y * (NTILE * TPB);// strip

    // ---- Stage A (128x128): fp32 -> bf16, 16B-chunk XOR swizzle ----
    const float4* x4 = (const float4*)(x + (size_t)rowBase * EMBED);
    #pragma unroll
    for (int i = 0; i < 8; i++) {
        const int flat = tid + 256 * i;               // 2048 chunks
        const int r = flat >> 4, c = flat & 15;
        const int swc = c ^ (r & 7);
        float4 a0 = x4[flat * 2], a1 = x4[flat * 2 + 1];
        uint4 pa = make_uint4(packbf(a0.x, a0.y), packbf(a0.z, a0.w),
                              packbf(a1.x, a1.y), packbf(a1.z, a1.w));
        *(uint4*)(smem + r * 256 + swc * 16) = pa;
    }

    // ---- Preload + stage B tile 0 (64 rows x 256B = 1024 chunks) ----
    float4 pf[4][2];
    {
        const float4* wt = (const float4*)(w + (size_t)itemBase0 * EMBED);
        #pragma unroll
        for (int i = 0; i < 4; i++) {
            const int flat = tid + 256 * i;
            pf[i][0] = wt[flat * 2];
            pf[i][1] = wt[flat * 2 + 1];
        }
        #pragma unroll
        for (int i = 0; i < 4; i++) {
            const int flat = tid + 256 * i;
            const int r = flat >> 4, c = flat & 15;
            const int swc = c ^ (r & 7);
            uint4 pb = make_uint4(packbf(pf[i][0].x, pf[i][0].y),
                                  packbf(pf[i][0].z, pf[i][0].w),
                                  packbf(pf[i][1].x, pf[i][1].y),
                                  packbf(pf[i][1].z, pf[i][1].w));
            *(uint4*)(smem + SM_B + r * 256 + swc * 16) = pb;
        }
    }
    __syncthreads();

    // ---- fragment addressing (warp tile 32x32: 4M x 2N warps) ----
    const int wm = wid >> 1;          // 0..3
    const int wn = wid & 1;           // 0..1
    const int la7  = lane & 7;
    const int lg8  = (lane >> 3) & 1;
    const int cgrp = lane >> 4;

    int Aoff[2], Asw[2];
    #pragma unroll
    for (int a = 0; a < 2; a++) {
        const int rr = wm * 32 + a * 16 + la7 + lg8 * 8;
        Aoff[a] = rr * 256;  Asw[a] = rr & 7;
    }
    int BoffR[2], Bsw[2];
    #pragma unroll
    for (int p = 0; p < 2; p++) {
        const int nr = wn * 32 + p * 16 + la7 + lg8 * 8;
        BoffR[p] = nr * 256;  Bsw[p] = nr & 7;
    }
    const int smRow0 = wm * 32 + lg8 * 8 + la7;
    const int chunk0 = wn * 4 + (lane >> 4);

    // ---- Tile loop: one sync per tile; copy-out lags one tile ----
    for (int n = 0; n < TPB; n++) {
        const int cur = n & 1;
        const int itemBase = itemBase0 + n * NTILE;

        if (n + 1 < TPB) {
            const float4* wt = (const float4*)(w + (size_t)(itemBase + NTILE) * EMBED);
            #pragma unroll
            for (int i = 0; i < 4; i++) {
                const int flat = tid + 256 * i;
                pf[i][0] = wt[flat * 2];
                pf[i][1] = wt[flat * 2 + 1];
            }
        }

        float d[2][4][4];
        #pragma unroll
        for (int a = 0; a < 2; a++)
            #pragma unroll
            for (int b = 0; b < 4; b++)
                #pragma unroll
                for (int q = 0; q < 4; q++) d[a][b][q] = 0.0f;

        const uint32_t bBase = sb + SM_B + cur * BTILE_SZ;
        #pragma unroll
        for (int ks = 0; ks < 8; ks++) {
            const int kc = ks * 2 + cgrp;
            uint32_t A[2][4], B[2][4];
            #pragma unroll
            for (int a = 0; a < 2; a++)
                LDSM4(A[a][0], A[a][1], A[a][2], A[a][3],
                      sb + Aoff[a] + ((kc ^ Asw[a]) << 4));
            #pragma unroll
            for (int p = 0; p < 2; p++)
                LDSM4(B[p][0], B[p][1], B[p][2], B[p][3],
                      bBase + BoffR[p] + ((kc ^ Bsw[p]) << 4));
            #pragma unroll
            for (int a = 0; a < 2; a++)
                #pragma unroll
                for (int b = 0; b < 4; b++)
                    MMA_BF16(d[a][b], A[a], B[b >> 1][b & 1], B[b >> 1][(b & 1) + 2]);
        }

        // stage next B tile into the other buffer
        if (n + 1 < TPB) {
            char* bnext = smem + SM_B + (cur ^ 1) * BTILE_SZ;
            #pragma unroll
            for (int i = 0; i < 4; i++) {
                const int flat = tid + 256 * i;
                const int r = flat >> 4, c = flat & 15;
                const int swc = c ^ (r & 7);
                uint4 pb = make_uint4(packbf(pf[i][0].x, pf[i][0].y),
                                      packbf(pf[i][0].z, pf[i][0].w),
                                      packbf(pf[i][1].x, pf[i][1].y),
                                      packbf(pf[i][1].z, pf[i][1].w));
                *(uint4*)(bnext + r * 256 + swc * 16) = pb;
            }
        }

        // epilogue part 1: pack + tilemax + stmatrix into stage[cur]
        const uint32_t stageBase = sb + SM_STAGE + cur * STAGE_SZ;
        const int colW = itemBase + wn * 32;
        #pragma unroll
        for (int a = 0; a < 2; a++) {
            uint32_t p[8];
            float m1 = -3.402823466e+38f, m2 = m1;
            #pragma unroll
            for (int b = 0; b < 4; b++) {
                p[b * 2 + 0] = packbf(d[a][b][0], d[a][b][1]);
                p[b * 2 + 1] = packbf(d[a][b][2], d[a][b][3]);
                m1 = fmaxf(m1, fmaxf(d[a][b][0], d[a][b][1]));
                m2 = fmaxf(m2, fmaxf(d[a][b][2], d[a][b][3]));
            }
            const int row = smRow0 + a * 16;
            #pragma unroll
            for (int bp = 0; bp < 2; bp++) {
                const int ch = chunk0 + bp * 2;
                const uint32_t addr = stageBase + row * 128
                                    + ((ch ^ (row & 7)) << 4);
                STSM4(addr, p[bp * 4 + 0], p[bp * 4 + 1],
                            p[bp * 4 + 2], p[bp * 4 + 3]);
            }
            m1 = fmaxf(m1, __shfl_xor_sync(0xFFFFFFFFu, m1, 1));
            m1 = fmaxf(m1, __shfl_xor_sync(0xFFFFFFFFu, m1, 2));
            m2 = fmaxf(m2, __shfl_xor_sync(0xFFFFFFFFu, m2, 1));
            m2 = fmaxf(m2, __shfl_xor_sync(0xFFFFFFFFu, m2, 2));
            if ((lane & 3) == 0) {
                const int r1 = rowBase + wm * 32 + a * 16 + (lane >> 2);
                const int grp = colW / TM;
                g_tilemax[(size_t)r1 * NTM + grp]       = m1;
                g_tilemax[(size_t)(r1 + 8) * NTM + grp] = m2;
            }
        }

        // copy-out of tile n-1 from stage[cur^1] (synced last iteration)
        if (n >= 1) {
            const char* prev = smem + SM_STAGE + (cur ^ 1) * STAGE_SZ;
            const int ib = itemBase - NTILE;
            #pragma unroll
            for (int i = 0; i < 4; i++) {
                const int flat = tid + 256 * i;       // 1024 chunks
                const int r = flat >> 3, c = flat & 7;
                const uint4 v = *(const uint4*)(prev + r * 128
                                                + ((c ^ (r & 7)) << 4));
                *(uint4*)((char*)g_logits
                          + ((size_t)(rowBase + r) * ITEMS + ib) * 2
                          + c * 16) = v;
            }
        }
        __syncthreads();
    }

    // final copy-out: tile TPB-1 from stage[(TPB-1)&1]
    {
        const char* prev = smem + SM_STAGE + ((TPB - 1) & 1) * STAGE_SZ;
        const int ib = itemBase0 + (TPB - 1) * NTILE;
        #pragma unroll
        for (int i = 0; i < 4; i++) {
            const int flat = tid + 256 * i;
            const int r = flat >> 3, c = flat & 7;
            const uint4 v = *(const uint4*)(prev + r * 128
                                            + ((c ^ (r & 7)) << 4));
            *(uint4*)((char*)g_logits
                      + ((size_t)(rowBase + r) * ITEMS + ib) * 2
                      + c * 16) = v;
        }
    }
}

// ---------------------------------------------------------------------------
// Top-k (unchanged; proven exact at ~125us).
// ---------------------------------------------------------------------------
#define TKT  256
#define CMAX 1024

__device__ __forceinline__ unsigned int fkey(float f) {
    unsigned int b = __float_as_uint(f);
    return b ^ ((b & 0x80000000u) ? 0xFFFFFFFFu : 0x80000000u);
}

__device__ __forceinline__ int wagg_append(int* ctr, bool pred, int ln) {
    const unsigned mask = __ballot_sync(0xFFFFFFFFu, pred);
    if (!pred) return -1;
    const int leader = __ffs(mask) - 1;
    int base = 0;
    if (ln == leader) base = atomicAdd(ctr, __popc(mask));
    base = __shfl_sync(mask, base, leader);
    return base + __popc(mask & ((1u << ln) - 1u));
}

__global__ __launch_bounds__(TKT)
void topk_kernel(const float* __restrict__ x, const float* __restrict__ w,
                 float* __restrict__ out)
{
    __shared__ float              s_x[EMBED];
    __shared__ float              s_max[TKT];
    __shared__ int                s_tiles[CMAX];
    __shared__ int                s_cidx[CMAX];
    __shared__ unsigned long long s_cand[CMAX];
    __shared__ int   s_nt, s_nc;
    __shared__ float s_eps;

    const int row = blockIdx.x;
    const int tid = threadIdx.x;
    const int wrp = tid >> 5, ln = tid & 31;
    const float* tm = g_tilemax + (size_t)row * NTM;

    if (tid < EMBED) s_x[tid] = x[(size_t)row * EMBED + tid];
    if (tid == 0) { s_nt = 0; s_nc = 0; }
    __syncthreads();

    if (tid < 32) {
        float ss = 0.0f;
        #pragma unroll
        for (int j = 0; j < 4; j++) { float v = s_x[tid * 4 + j]; ss += v * v; }
        #pragma unroll
        for (int o = 16; o > 0; o >>= 1) ss += __shfl_xor_sync(0xFFFFFFFFu, ss, o);
        if (tid == 0) s_eps = 1.05f * (1.0f / 128.0f) * sqrtf(ss) * 1.1313708f;
    }

    float m = -3.402823466e+38f;
    #pragma unroll
    for (int j = 0; j < 32; j++) m = fmaxf(m, tm[tid + TKT * j]);
    s_max[tid] = m;
    __syncthreads();

    for (int k = 2; k <= TKT; k <<= 1) {
        for (int j = k >> 1; j > 0; j >>= 1) {
            const int ixj = tid ^ j;
            if (ixj > tid) {
                const bool desc = ((tid & k) == 0);
                const float a = s_max[tid], b = s_max[ixj];
                if (desc ? (a < b) : (a > b)) { s_max[tid] = b; s_max[ixj] = a; }
            }
            __syncthreads();
        }
    }
    const float thr = s_max[TOPK - 1] - 1.05f * s_eps - 1e-5f;
    __syncthreads();

    #pragma unroll
    for (int j = 0; j < 32; j++) {
        const int g = tid + TKT * j;
        const bool q = (tm[g] >= thr);
        const int p = wagg_append(&s_nt, q, ln);
        if (q && p < CMAX) s_tiles[p] = g;
    }
    __syncthreads();
    const int ntl = s_nt < CMAX ? s_nt : CMAX;

    const __nv_bfloat16* lg = g_logits + (size_t)row * ITEMS;
    for (int i = wrp; i < ntl; i += TKT / 32) {
        const int idx = s_tiles[i] * TM + ln;
        const float v = __bfloat162float(lg[idx]);
        const bool q = (v >= thr);
        const int p = wagg_append(&s_nc, q, ln);
        if (q && p < CMAX) s_cidx[p] = idx;
    }
    __syncthreads();
    const int C = s_nc < CMAX ? s_nc : CMAX;

    for (int i = tid; i < C; i += TKT) {
        const int idx = s_cidx[i];
        const float* wr = w + (size_t)idx * EMBED;
        float s = 0.0f;
        #pragma unroll 8
        for (int k4 = 0; k4 < EMBED / 4; k4++) {
            const float4 wv = ((const float4*)wr)[k4];
            s = fmaf(s_x[k4 * 4 + 0], wv.x, s);
            s = fmaf(s_x[k4 * 4 + 1], wv.y, s);
            s = fmaf(s_x[k4 * 4 + 2], wv.z, s);
            s = fmaf(s_x[k4 * 4 + 3], wv.w, s);
        }
        s_cand[i] = ((unsigned long long)fkey(s) << 32) |
                    (unsigned int)(~(unsigned int)idx);
    }
    __syncthreads();

    int P = 128;
    while (P < C) P <<= 1;
    for (int i = tid; i < P; i += TKT)
        if (i >= C) s_cand[i] = 0ULL;
    __syncthreads();

    for (int k = 2; k <= P; k <<= 1) {
        for (int j = k >> 1; j > 0; j >>= 1) {
            for (int i = tid; i < P; i += TKT) {
                const int ixj = i ^ j;
                if (ixj > i) {
                    const bool desc = ((i & k) == 0);
                    const unsigned long long a = s_cand[i], b = s_cand[ixj];
                    if (desc ? (a < b) : (a > b)) { s_cand[i] = b; s_cand[ixj] = a; }
                }
            }
            __syncthreads();
        }
    }

    if (tid < TOPK) {
        const unsigned int low = (unsigned int)s_cand[tid];
        out[(size_t)row * TOPK + tid] = (float)(~low);
    }
}

// ---------------------------------------------------------------------------
extern "C" void kernel_launch(void* const* d_in, const int* in_sizes, int n_in,
                              void* d_out, int out_size)
{
    const float* x = nullptr;
    const float* w = nullptr;
    for (int i = 0; i < n_in; i++) {
        if (in_sizes[i] == BATCH * EMBED)      x = (const float*)d_in[i];
        else if (in_sizes[i] == ITEMS * EMBED) w = (const float*)d_in[i];
    }
    float* out = (float*)d_out;

    static bool attr_set = false;
    if (!attr_set) {
        cudaFuncSetAttribute(gemm_screen,
                             cudaFuncAttributeMaxDynamicSharedMemorySize, SM_TOTAL);
        attr_set = true;
    }

    dim3 grid(BATCH / GMB, ITEMS / (NTILE * TPB));   // (8, 256) panel-fast
    gemm_screen<<<grid, 256, SM_TOTAL>>>(x, w);
    topk_kernel<<<BATCH, TKT>>>(x, w, out);
}

// round 9
// speedup vs baseline: 5.3172x; 1.1178x over previous
#include <cuda_runtime.h>
#include <cuda_bf16.h>
#include <cstdint>

#define BATCH    1024
#define EMBED    128
#define ITEMS    262144
#define TOPK     100
#define TM       32               // tile-max granularity (items)
#define NTM      (ITEMS/TM)       // 8192 tile maxima per row

#define NTILE    64               // items per GEMM N-tile
#define TPB      16               // N-tiles per CTA
#define GMB      128              // M rows per CTA

__device__ __nv_bfloat16 g_logits[(size_t)BATCH * ITEMS];
__device__ float         g_tilemax[(size_t)BATCH * NTM];
__device__ __nv_bfloat16 g_wbf[(size_t)ITEMS * EMBED];   // pre-converted w

// ---------------------------------------------------------------------------
__device__ __forceinline__ uint32_t smem_u32(const void* p) {
    uint32_t a;
    asm("{ .reg .u64 t; cvta.to.shared.u64 t, %1; cvt.u32.u64 %0, t; }"
        : "=r"(a) : "l"(p));
    return a;
}
__device__ __forceinline__ uint32_t packbf(float lo, float hi) {
    uint32_t r;
    asm("cvt.rn.bf16x2.f32 %0, %1, %2;" : "=r"(r) : "f"(hi), "f"(lo));
    return r;
}

#define LDSM4(r0, r1, r2, r3, a)                                              \
    asm volatile("ldmatrix.sync.aligned.m8n8.x4.shared.b16 {%0,%1,%2,%3}, [%4];" \
        : "=r"(r0), "=r"(r1), "=r"(r2), "=r"(r3) : "r"(a))

#define STSM4(a, r0, r1, r2, r3)                                              \
    asm volatile("stmatrix.sync.aligned.m8n8.x4.shared.b16 [%0], {%1,%2,%3,%4};" \
        :: "r"(a), "r"(r0), "r"(r1), "r"(r2), "r"(r3) : "memory")

#define MMA_BF16(d, A, b0, b1)                                                \
    asm volatile("mma.sync.aligned.m16n8k16.row.col.f32.bf16.bf16.f32 "       \
        "{%0,%1,%2,%3}, {%4,%5,%6,%7}, {%8,%9}, {%0,%1,%2,%3};"               \
        : "+f"((d)[0]), "+f"((d)[1]), "+f"((d)[2]), "+f"((d)[3])              \
        : "r"((A)[0]), "r"((A)[1]), "r"((A)[2]), "r"((A)[3]),                 \
          "r"(b0), "r"(b1))

#define CP_ASYNC16(dst, src)                                                  \
    asm volatile("cp.async.cg.shared.global [%0], [%1], 16;"                  \
        :: "r"(dst), "l"(src) : "memory")
#define CP_COMMIT()  asm volatile("cp.async.commit_group;" ::: "memory")
#define CP_WAIT0()   asm volatile("cp.async.wait_group 0;" ::: "memory")

// ---------------------------------------------------------------------------
// One-time w conversion: fp32 -> bf16 (row-major, same layout).
// ---------------------------------------------------------------------------
__global__ __launch_bounds__(256)
void convert_w(const float* __restrict__ w)
{
    const size_t i = (size_t)blockIdx.x * blockDim.x + threadIdx.x; // 8 floats
    const float4* w4 = (const float4*)w;
    const float4 a = w4[i * 2], b = w4[i * 2 + 1];
    ((uint4*)g_wbf)[i] = make_uint4(packbf(a.x, a.y), packbf(a.z, a.w),
                                    packbf(b.x, b.y), packbf(b.z, b.w));
}

// ---------------------------------------------------------------------------
// Screening GEMM (2 CTAs/SM): 128(M) x 64(N) x 16 tiles, 8 warps (4M x 2N),
// warp tile 32x32. A resident 32KB; B double-buffered 2x16KB loaded with
// cp.async from pre-converted bf16 w; stage double-buffered 2x16KB.
// ---------------------------------------------------------------------------
#define SM_B      32768
#define SM_STAGE  65536
#define BTILE_SZ  16384
#define STAGE_SZ  16384
#define SM_TOTAL  98304

__global__ __launch_bounds__(256, 2)
void gemm_screen(const float* __restrict__ x)
{
    extern __shared__ char smem[];
    const uint32_t sb = smem_u32(smem);
    const int tid  = threadIdx.x;
    const int lane = tid & 31;
    const int wid  = tid >> 5;
    const int rowBase   = blockIdx.x * GMB;
    const int itemBase0 = blockIdx.y * (NTILE * TPB);

    // per-thread B chunk coordinates (4 chunks of 16B per tile)
    int bR[4], bC[4];
    uint32_t bDst[4];
    #pragma unroll
    for (int i = 0; i < 4; i++) {
        const int flat = tid + 256 * i;      // 0..1023
        bR[i] = flat >> 4;                   // row 0..63
        bC[i] = flat & 15;                   // 16B col unit
        bDst[i] = sb + SM_B + bR[i] * 256 + ((bC[i] ^ (bR[i] & 7)) << 4);
    }

    // ---- Stage A (128x128): fp32 -> bf16, 16B-chunk XOR swizzle ----
    const float4* x4 = (const float4*)(x + (size_t)rowBase * EMBED);
    #pragma unroll
    for (int i = 0; i < 8; i++) {
        const int flat = tid + 256 * i;
        const int r = flat >> 4, c = flat & 15;
        const int swc = c ^ (r & 7);
        float4 a0 = x4[flat * 2], a1 = x4[flat * 2 + 1];
        uint4 pa = make_uint4(packbf(a0.x, a0.y), packbf(a0.z, a0.w),
                              packbf(a1.x, a1.y), packbf(a1.z, a1.w));
        *(uint4*)(smem + r * 256 + swc * 16) = pa;
    }

    // ---- cp.async B tile 0 into buffer 0 ----
    #pragma unroll
    for (int i = 0; i < 4; i++) {
        const char* src = (const char*)g_wbf
                        + (size_t)(itemBase0 + bR[i]) * 256 + bC[i] * 16;
        CP_ASYNC16(bDst[i], src);
    }
    CP_COMMIT();
    CP_WAIT0();
    __syncthreads();

    // ---- fragment addressing (warp tile 32x32: 4M x 2N warps) ----
    const int wm = wid >> 1;
    const int wn = wid & 1;
    const int la7  = lane & 7;
    const int lg8  = (lane >> 3) & 1;
    const int cgrp = lane >> 4;

    int Aoff[2], Asw[2];
    #pragma unroll
    for (int a = 0; a < 2; a++) {
        const int rr = wm * 32 + a * 16 + la7 + lg8 * 8;
        Aoff[a] = rr * 256;  Asw[a] = rr & 7;
    }
    int BoffR[2], Bsw[2];
    #pragma unroll
    for (int p = 0; p < 2; p++) {
        const int nr = wn * 32 + p * 16 + la7 + lg8 * 8;
        BoffR[p] = nr * 256;  Bsw[p] = nr & 7;
    }
    const int smRow0 = wm * 32 + lg8 * 8 + la7;
    const int chunk0 = wn * 4 + (lane >> 4);

    // ---- Tile loop ----
    for (int n = 0; n < TPB; n++) {
        const int cur = n & 1;
        const int itemBase = itemBase0 + n * NTILE;

        // async-load next B tile into the other buffer (overlaps everything)
        if (n + 1 < TPB) {
            const uint32_t flip = (cur ^ 1) * BTILE_SZ;
            #pragma unroll
            for (int i = 0; i < 4; i++) {
                const char* src = (const char*)g_wbf
                                + (size_t)(itemBase + NTILE + bR[i]) * 256
                                + bC[i] * 16;
                CP_ASYNC16(bDst[i] + flip, src);
            }
            CP_COMMIT();
        }

        float d[2][4][4];
        #pragma unroll
        for (int a = 0; a < 2; a++)
            #pragma unroll
            for (int b = 0; b < 4; b++)
                #pragma unroll
                for (int q = 0; q < 4; q++) d[a][b][q] = 0.0f;

        const uint32_t bBase = sb + SM_B + cur * BTILE_SZ;
        #pragma unroll
        for (int ks = 0; ks < 8; ks++) {
            const int kc = ks * 2 + cgrp;
            uint32_t A[2][4], B[2][4];
            #pragma unroll
            for (int a = 0; a < 2; a++)
                LDSM4(A[a][0], A[a][1], A[a][2], A[a][3],
                      sb + Aoff[a] + ((kc ^ Asw[a]) << 4));
            #pragma unroll
            for (int p = 0; p < 2; p++)
                LDSM4(B[p][0], B[p][1], B[p][2], B[p][3],
                      bBase + BoffR[p] + ((kc ^ Bsw[p]) << 4));
            #pragma unroll
            for (int a = 0; a < 2; a++)
                #pragma unroll
                for (int b = 0; b < 4; b++)
                    MMA_BF16(d[a][b], A[a], B[b >> 1][b & 1], B[b >> 1][(b & 1) + 2]);
        }

        // epilogue: pack + tilemax + stmatrix into stage[cur]
        const uint32_t stageBase = sb + SM_STAGE + cur * STAGE_SZ;
        const int colW = itemBase + wn * 32;
        #pragma unroll
        for (int a = 0; a < 2; a++) {
            uint32_t p[8];
            float m1 = -3.402823466e+38f, m2 = m1;
            #pragma unroll
            for (int b = 0; b < 4; b++) {
                p[b * 2 + 0] = packbf(d[a][b][0], d[a][b][1]);
                p[b * 2 + 1] = packbf(d[a][b][2], d[a][b][3]);
                m1 = fmaxf(m1, fmaxf(d[a][b][0], d[a][b][1]));
                m2 = fmaxf(m2, fmaxf(d[a][b][2], d[a][b][3]));
            }
            const int row = smRow0 + a * 16;
            #pragma unroll
            for (int bp = 0; bp < 2; bp++) {
                const int ch = chunk0 + bp * 2;
                const uint32_t addr = stageBase + row * 128
                                    + ((ch ^ (row & 7)) << 4);
                STSM4(addr, p[bp * 4 + 0], p[bp * 4 + 1],
                            p[bp * 4 + 2], p[bp * 4 + 3]);
            }
            m1 = fmaxf(m1, __shfl_xor_sync(0xFFFFFFFFu, m1, 1));
            m1 = fmaxf(m1, __shfl_xor_sync(0xFFFFFFFFu, m1, 2));
            m2 = fmaxf(m2, __shfl_xor_sync(0xFFFFFFFFu, m2, 1));
            m2 = fmaxf(m2, __shfl_xor_sync(0xFFFFFFFFu, m2, 2));
            if ((lane & 3) == 0) {
                const int r1 = rowBase + wm * 32 + a * 16 + (lane >> 2);
                const int grp = colW / TM;
                g_tilemax[(size_t)r1 * NTM + grp]       = m1;
                g_tilemax[(size_t)(r1 + 8) * NTM + grp] = m2;
            }
        }

        // copy-out of tile n-1 from stage[cur^1]
        if (n >= 1) {
            const char* prev = smem + SM_STAGE + (cur ^ 1) * STAGE_SZ;
            const int ib = itemBase - NTILE;
            #pragma unroll
            for (int i = 0; i < 4; i++) {
                const int flat = tid + 256 * i;
                const int r = flat >> 3, c = flat & 7;
                const uint4 v = *(const uint4*)(prev + r * 128
                                                + ((c ^ (r & 7)) << 4));
                *(uint4*)((char*)g_logits
                          + ((size_t)(rowBase + r) * ITEMS + ib) * 2
                          + c * 16) = v;
            }
        }

        if (n + 1 < TPB) CP_WAIT0();
        __syncthreads();
    }

    // final copy-out: tile TPB-1
    {
        const char* prev = smem + SM_STAGE + ((TPB - 1) & 1) * STAGE_SZ;
        const int ib = itemBase0 + (TPB - 1) * NTILE;
        #pragma unroll
        for (int i = 0; i < 4; i++) {
            const int flat = tid + 256 * i;
            const int r = flat >> 3, c = flat & 7;
            const uint4 v = *(const uint4*)(prev + r * 128
                                            + ((c ^ (r & 7)) << 4));
            *(uint4*)((char*)g_logits
                      + ((size_t)(rowBase + r) * ITEMS + ib) * 2
                      + c * 16) = v;
        }
    }
}

// ---------------------------------------------------------------------------
// Top-k (structure proven; tm pass now float4 / MLP-8).
// ---------------------------------------------------------------------------
#define TKT  256
#define CMAX 1024

__device__ __forceinline__ unsigned int fkey(float f) {
    unsigned int b = __float_as_uint(f);
    return b ^ ((b & 0x80000000u) ? 0xFFFFFFFFu : 0x80000000u);
}

__device__ __forceinline__ int wagg_append(int* ctr, bool pred, int ln) {
    const unsigned mask = __ballot_sync(0xFFFFFFFFu, pred);
    if (!pred) return -1;
    const int leader = __ffs(mask) - 1;
    int base = 0;
    if (ln == leader) base = atomicAdd(ctr, __popc(mask));
    base = __shfl_sync(mask, base, leader);
    return base + __popc(mask & ((1u << ln) - 1u));
}

__global__ __launch_bounds__(TKT)
void topk_kernel(const float* __restrict__ x, const float* __restrict__ w,
                 float* __restrict__ out)
{
    __shared__ float              s_x[EMBED];
    __shared__ float              s_max[TKT];
    __shared__ int                s_tiles[CMAX];
    __shared__ int                s_cidx[CMAX];
    __shared__ unsigned long long s_cand[CMAX];
    __shared__ int   s_nt, s_nc;
    __shared__ float s_eps;

    const int row = blockIdx.x;
    const int tid = threadIdx.x;
    const int wrp = tid >> 5, ln = tid & 31;
    const float4* tm4 = (const float4*)(g_tilemax + (size_t)row * NTM);

    if (tid < EMBED) s_x[tid] = x[(size_t)row * EMBED + tid];
    if (tid == 0) { s_nt = 0; s_nc = 0; }
    __syncthreads();

    if (tid < 32) {
        float ss = 0.0f;
        #pragma unroll
        for (int j = 0; j < 4; j++) { float v = s_x[tid * 4 + j]; ss += v * v; }
        #pragma unroll
        for (int o = 16; o > 0; o >>= 1) ss += __shfl_xor_sync(0xFFFFFFFFu, ss, o);
        if (tid == 0) s_eps = 1.05f * (1.0f / 128.0f) * sqrtf(ss) * 1.1313708f;
    }

    // group max over thread-contiguous 32 tiles (8 x LDG.128, high MLP)
    float m = -3.402823466e+38f;
    #pragma unroll
    for (int j = 0; j < 8; j++) {
        const float4 v = tm4[tid * 8 + j];
        m = fmaxf(m, fmaxf(fmaxf(v.x, v.y), fmaxf(v.z, v.w)));
    }
    s_max[tid] = m;
    __syncthreads();

    for (int k = 2; k <= TKT; k <<= 1) {
        for (int j = k >> 1; j > 0; j >>= 1) {
            const int ixj = tid ^ j;
            if (ixj > tid) {
                const bool desc = ((tid & k) == 0);
                const float a = s_max[tid], b = s_max[ixj];
                if (desc ? (a < b) : (a > b)) { s_max[tid] = b; s_max[ixj] = a; }
            }
            __syncthreads();
        }
    }
    const float thr = s_max[TOPK - 1] - 1.05f * s_eps - 1e-5f;
    __syncthreads();

    // qualifying tiles (float4 scan + warp-aggregated append)
    #pragma unroll
    for (int j = 0; j < 8; j++) {
        const float4 v = tm4[tid * 8 + j];
        const int base = tid * 32 + j * 4;
        #pragma unroll
        for (int c = 0; c < 4; c++) {
            const float tv = (c == 0) ? v.x : (c == 1) ? v.y : (c == 2) ? v.z : v.w;
            const bool q = (tv >= thr);
            const int p = wagg_append(&s_nt, q, ln);
            if (q && p < CMAX) s_tiles[p] = base + c;
        }
    }
    __syncthreads();
    const int ntl = s_nt < CMAX ? s_nt : CMAX;

    const __nv_bfloat16* lg = g_logits + (size_t)row * ITEMS;
    for (int i = wrp; i < ntl; i += TKT / 32) {
        const int idx = s_tiles[i] * TM + ln;
        const float v = __bfloat162float(lg[idx]);
        const bool q = (v >= thr);
        const int p = wagg_append(&s_nc, q, ln);
        if (q && p < CMAX) s_cidx[p] = idx;
    }
    __syncthreads();
    const int C = s_nc < CMAX ? s_nc : CMAX;

    // exact rescore: one thread per candidate, sequential fmaf k=0..127
    for (int i = tid; i < C; i += TKT) {
        const int idx = s_cidx[i];
        const float* wr = w + (size_t)idx * EMBED;
        float s = 0.0f;
        #pragma unroll 8
        for (int k4 = 0; k4 < EMBED / 4; k4++) {
            const float4 wv = ((const float4*)wr)[k4];
            s = fmaf(s_x[k4 * 4 + 0], wv.x, s);
            s = fmaf(s_x[k4 * 4 + 1], wv.y, s);
            s = fmaf(s_x[k4 * 4 + 2], wv.z, s);
            s = fmaf(s_x[k4 * 4 + 3], wv.w, s);
        }
        s_cand[i] = ((unsigned long long)fkey(s) << 32) |
                    (unsigned int)(~(unsigned int)idx);
    }
    __syncthreads();

    int P = 128;
    while (P < C) P <<= 1;
    for (int i = tid; i < P; i += TKT)
        if (i >= C) s_cand[i] = 0ULL;
    __syncthreads();

    for (int k = 2; k <= P; k <<= 1) {
        for (int j = k >> 1; j > 0; j >>= 1) {
            for (int i = tid; i < P; i += TKT) {
                const int ixj = i ^ j;
                if (ixj > i) {
                    const bool desc = ((i & k) == 0);
                    const unsigned long long a = s_cand[i], b = s_cand[ixj];
                    if (desc ? (a < b) : (a > b)) { s_cand[i] = b; s_cand[ixj] = a; }
                }
            }
            __syncthreads();
        }
    }

    if (tid < TOPK) {
        const unsigned int low = (unsigned int)s_cand[tid];
        out[(size_t)row * TOPK + tid] = (float)(~low);
    }
}

// ---------------------------------------------------------------------------
extern "C" void kernel_launch(void* const* d_in, const int* in_sizes, int n_in,
                              void* d_out, int out_size)
{
    const float* x = nullptr;
    const float* w = nullptr;
    for (int i = 0; i < n_in; i++) {
        if (in_sizes[i] == BATCH * EMBED)      x = (const float*)d_in[i];
        else if (in_sizes[i] == ITEMS * EMBED) w = (const float*)d_in[i];
    }
    float* out = (float*)d_out;

    static bool attr_set = false;
    if (!attr_set) {
        cudaFuncSetAttribute(gemm_screen,
                             cudaFuncAttributeMaxDynamicSharedMemorySize, SM_TOTAL);
        attr_set = true;
    }

    convert_w<<<(ITEMS * EMBED / 8) / 256, 256>>>(w);
    dim3 grid(BATCH / GMB, ITEMS / (NTILE * TPB));   // (8, 256)
    gemm_screen<<<grid, 256, SM_TOTAL>>>(x);
    topk_kernel<<<BATCH, TKT>>>(x, w, out);
}

// round 10
// speedup vs baseline: 5.8803x; 1.1059x over previous
#include <cuda_runtime.h>
#include <cuda_fp16.h>
#include <cstdint>

#define BATCH    1024
#define EMBED    128
#define ITEMS    262144
#define TOPK     100
#define TM       32               // tile-max granularity (items)
#define NTM      (ITEMS/TM)       // 8192 tile maxima per row

#define NTILE    64               // items per GEMM N-tile
#define TPB      16               // N-tiles per CTA
#define GMB      128              // M rows per CTA

__device__ __half g_logits[(size_t)BATCH * ITEMS];
__device__ float  g_tilemax[(size_t)BATCH * NTM];
__device__ __half g_whf[(size_t)ITEMS * EMBED];   // pre-converted w (fp16)

// ---------------------------------------------------------------------------
__device__ __forceinline__ uint32_t smem_u32(const void* p) {
    uint32_t a;
    asm("{ .reg .u64 t; cvta.to.shared.u64 t, %1; cvt.u32.u64 %0, t; }"
        : "=r"(a) : "l"(p));
    return a;
}
__device__ __forceinline__ uint32_t packhf(float lo, float hi) {
    uint32_t r;
    asm("cvt.rn.f16x2.f32 %0, %1, %2;" : "=r"(r) : "f"(hi), "f"(lo));
    return r;
}

#define LDSM4(r0, r1, r2, r3, a)                                              \
    asm volatile("ldmatrix.sync.aligned.m8n8.x4.shared.b16 {%0,%1,%2,%3}, [%4];" \
        : "=r"(r0), "=r"(r1), "=r"(r2), "=r"(r3) : "r"(a))

#define STSM4(a, r0, r1, r2, r3)                                              \
    asm volatile("stmatrix.sync.aligned.m8n8.x4.shared.b16 [%0], {%1,%2,%3,%4};" \
        :: "r"(a), "r"(r0), "r"(r1), "r"(r2), "r"(r3) : "memory")

#define MMA_F16(d, A, b0, b1)                                                 \
    asm volatile("mma.sync.aligned.m16n8k16.row.col.f32.f16.f16.f32 "         \
        "{%0,%1,%2,%3}, {%4,%5,%6,%7}, {%8,%9}, {%0,%1,%2,%3};"               \
        : "+f"((d)[0]), "+f"((d)[1]), "+f"((d)[2]), "+f"((d)[3])              \
        : "r"((A)[0]), "r"((A)[1]), "r"((A)[2]), "r"((A)[3]),                 \
          "r"(b0), "r"(b1))

#define CP_ASYNC16(dst, src)                                                  \
    asm volatile("cp.async.cg.shared.global [%0], [%1], 16;"                  \
        :: "r"(dst), "l"(src) : "memory")
#define CP_COMMIT()  asm volatile("cp.async.commit_group;" ::: "memory")
#define CP_WAIT0()   asm volatile("cp.async.wait_group 0;" ::: "memory")

// ---------------------------------------------------------------------------
// One-time w conversion: fp32 -> fp16 (row-major).
// ---------------------------------------------------------------------------
__global__ __launch_bounds__(256)
void convert_w(const float* __restrict__ w)
{
    const size_t i = (size_t)blockIdx.x * blockDim.x + threadIdx.x; // 8 floats
    const float4* w4 = (const float4*)w;
    const float4 a = w4[i * 2], b = w4[i * 2 + 1];
    ((uint4*)g_whf)[i] = make_uint4(packhf(a.x, a.y), packhf(a.z, a.w),
                                    packhf(b.x, b.y), packhf(b.z, b.w));
}

// ---------------------------------------------------------------------------
// Screening GEMM (2 CTAs/SM): fp16 HMMA, 128(M) x 64(N) x 16 tiles,
// 8 warps (4M x 2N), warp tile 32x32. A resident 32KB; B double-buffered
// 2x16KB via cp.async from fp16 w; stage double-buffered 2x16KB.
// ---------------------------------------------------------------------------
#define SM_B      32768
#define SM_STAGE  65536
#define BTILE_SZ  16384
#define STAGE_SZ  16384
#define SM_TOTAL  98304

__global__ __launch_bounds__(256, 2)
void gemm_screen(const float* __restrict__ x)
{
    extern __shared__ char smem[];
    const uint32_t sb = smem_u32(smem);
    const int tid  = threadIdx.x;
    const int lane = tid & 31;
    const int wid  = tid >> 5;
    const int rowBase   = blockIdx.x * GMB;
    const int itemBase0 = blockIdx.y * (NTILE * TPB);

    int bR[4], bC[4];
    uint32_t bDst[4];
    #pragma unroll
    for (int i = 0; i < 4; i++) {
        const int flat = tid + 256 * i;
        bR[i] = flat >> 4;
        bC[i] = flat & 15;
        bDst[i] = sb + SM_B + bR[i] * 256 + ((bC[i] ^ (bR[i] & 7)) << 4);
    }

    // ---- Stage A (128x128): fp32 -> fp16, 16B-chunk XOR swizzle ----
    const float4* x4 = (const float4*)(x + (size_t)rowBase * EMBED);
    #pragma unroll
    for (int i = 0; i < 8; i++) {
        const int flat = tid + 256 * i;
        const int r = flat >> 4, c = flat & 15;
        const int swc = c ^ (r & 7);
        float4 a0 = x4[flat * 2], a1 = x4[flat * 2 + 1];
        uint4 pa = make_uint4(packhf(a0.x, a0.y), packhf(a0.z, a0.w),
                              packhf(a1.x, a1.y), packhf(a1.z, a1.w));
        *(uint4*)(smem + r * 256 + swc * 16) = pa;
    }

    // ---- cp.async B tile 0 ----
    #pragma unroll
    for (int i = 0; i < 4; i++) {
        const char* src = (const char*)g_whf
                        + (size_t)(itemBase0 + bR[i]) * 256 + bC[i] * 16;
        CP_ASYNC16(bDst[i], src);
    }
    CP_COMMIT();
    CP_WAIT0();
    __syncthreads();

    const int wm = wid >> 1;
    const int wn = wid & 1;
    const int la7  = lane & 7;
    const int lg8  = (lane >> 3) & 1;
    const int cgrp = lane >> 4;

    int Aoff[2], Asw[2];
    #pragma unroll
    for (int a = 0; a < 2; a++) {
        const int rr = wm * 32 + a * 16 + la7 + lg8 * 8;
        Aoff[a] = rr * 256;  Asw[a] = rr & 7;
    }
    int BoffR[2], Bsw[2];
    #pragma unroll
    for (int p = 0; p < 2; p++) {
        const int nr = wn * 32 + p * 16 + la7 + lg8 * 8;
        BoffR[p] = nr * 256;  Bsw[p] = nr & 7;
    }
    const int smRow0 = wm * 32 + lg8 * 8 + la7;
    const int chunk0 = wn * 4 + (lane >> 4);

    for (int n = 0; n < TPB; n++) {
        const int cur = n & 1;
        const int itemBase = itemBase0 + n * NTILE;

        if (n + 1 < TPB) {
            const uint32_t flip = (cur ^ 1) * BTILE_SZ;
            #pragma unroll
            for (int i = 0; i < 4; i++) {
                const char* src = (const char*)g_whf
                                + (size_t)(itemBase + NTILE + bR[i]) * 256
                                + bC[i] * 16;
                CP_ASYNC16(bDst[i] + flip, src);
            }
            CP_COMMIT();
        }

        float d[2][4][4];
        #pragma unroll
        for (int a = 0; a < 2; a++)
            #pragma unroll
            for (int b = 0; b < 4; b++)
                #pragma unroll
                for (int q = 0; q < 4; q++) d[a][b][q] = 0.0f;

        const uint32_t bBase = sb + SM_B + cur * BTILE_SZ;
        #pragma unroll
        for (int ks = 0; ks < 8; ks++) {
            const int kc = ks * 2 + cgrp;
            uint32_t A[2][4], B[2][4];
            #pragma unroll
            for (int a = 0; a < 2; a++)
                LDSM4(A[a][0], A[a][1], A[a][2], A[a][3],
                      sb + Aoff[a] + ((kc ^ Asw[a]) << 4));
            #pragma unroll
            for (int p = 0; p < 2; p++)
                LDSM4(B[p][0], B[p][1], B[p][2], B[p][3],
                      bBase + BoffR[p] + ((kc ^ Bsw[p]) << 4));
            #pragma unroll
            for (int a = 0; a < 2; a++)
                #pragma unroll
                for (int b = 0; b < 4; b++)
                    MMA_F16(d[a][b], A[a], B[b >> 1][b & 1], B[b >> 1][(b & 1) + 2]);
        }

        const uint32_t stageBase = sb + SM_STAGE + cur * STAGE_SZ;
        const int colW = itemBase + wn * 32;
        #pragma unroll
        for (int a = 0; a < 2; a++) {
            uint32_t p[8];
            float m1 = -3.402823466e+38f, m2 = m1;
            #pragma unroll
            for (int b = 0; b < 4; b++) {
                p[b * 2 + 0] = packhf(d[a][b][0], d[a][b][1]);
                p[b * 2 + 1] = packhf(d[a][b][2], d[a][b][3]);
                m1 = fmaxf(m1, fmaxf(d[a][b][0], d[a][b][1]));
                m2 = fmaxf(m2, fmaxf(d[a][b][2], d[a][b][3]));
            }
            const int row = smRow0 + a * 16;
            #pragma unroll
            for (int bp = 0; bp < 2; bp++) {
                const int ch = chunk0 + bp * 2;
                const uint32_t addr = stageBase + row * 128
                                    + ((ch ^ (row & 7)) << 4);
                STSM4(addr, p[bp * 4 + 0], p[bp * 4 + 1],
                            p[bp * 4 + 2], p[bp * 4 + 3]);
            }
            m1 = fmaxf(m1, __shfl_xor_sync(0xFFFFFFFFu, m1, 1));
            m1 = fmaxf(m1, __shfl_xor_sync(0xFFFFFFFFu, m1, 2));
            m2 = fmaxf(m2, __shfl_xor_sync(0xFFFFFFFFu, m2, 1));
            m2 = fmaxf(m2, __shfl_xor_sync(0xFFFFFFFFu, m2, 2));
            if ((lane & 3) == 0) {
                const int r1 = rowBase + wm * 32 + a * 16 + (lane >> 2);
                const int grp = colW / TM;
                g_tilemax[(size_t)r1 * NTM + grp]       = m1;
                g_tilemax[(size_t)(r1 + 8) * NTM + grp] = m2;
            }
        }

        if (n >= 1) {
            const char* prev = smem + SM_STAGE + (cur ^ 1) * STAGE_SZ;
            const int ib = itemBase - NTILE;
            #pragma unroll
            for (int i = 0; i < 4; i++) {
                const int flat = tid + 256 * i;
                const int r = flat >> 3, c = flat & 7;
                const uint4 v = *(const uint4*)(prev + r * 128
                                                + ((c ^ (r & 7)) << 4));
                *(uint4*)((char*)g_logits
                          + ((size_t)(rowBase + r) * ITEMS + ib) * 2
                          + c * 16) = v;
            }
        }

        if (n + 1 < TPB) CP_WAIT0();
        __syncthreads();
    }

    {
        const char* prev = smem + SM_STAGE + ((TPB - 1) & 1) * STAGE_SZ;
        const int ib = itemBase0 + (TPB - 1) * NTILE;
        #pragma unroll
        for (int i = 0; i < 4; i++) {
            const int flat = tid + 256 * i;
            const int r = flat >> 3, c = flat & 7;
            const uint4 v = *(const uint4*)(prev + r * 128
                                            + ((c ^ (r & 7)) << 4));
            *(uint4*)((char*)g_logits
                      + ((size_t)(rowBase + r) * ITEMS + ib) * 2
                      + c * 16) = v;
        }
    }
}

// ---------------------------------------------------------------------------
// Top-k. fp16 screen error bound: B = 2^-11 * ||x||2 * 0.1*sqrt(128)
// (subnormal absolute errors negligible; fp32 accumulation covered by 1.05).
// eps = 2.1*B. Threshold t via bisection on group maxima with invariant
// cnt(>= lo) >= 100  =>  >= 100 items with screen >= t  =>  exact 100th
// value >= t - B  =>  every true top-100 screen >= t - 2B > t - eps*1.05.
// ---------------------------------------------------------------------------
#define TKT  256
#define CMAX 1024

__device__ __forceinline__ unsigned int fkey(float f) {
    unsigned int b = __float_as_uint(f);
    return b ^ ((b & 0x80000000u) ? 0xFFFFFFFFu : 0x80000000u);
}

__device__ __forceinline__ int wagg_append(int* ctr, bool pred, int ln) {
    const unsigned mask = __ballot_sync(0xFFFFFFFFu, pred);
    if (!pred) return -1;
    const int leader = __ffs(mask) - 1;
    int base = 0;
    if (ln == leader) base = atomicAdd(ctr, __popc(mask));
    base = __shfl_sync(mask, base, leader);
    return base + __popc(mask & ((1u << ln) - 1u));
}

__global__ __launch_bounds__(TKT)
void topk_kernel(const float* __restrict__ x, const float* __restrict__ w,
                 float* __restrict__ out)
{
    __shared__ float              s_x[EMBED];
    __shared__ float              s_wmax[8], s_wmin[8];
    __shared__ int                s_tiles[CMAX];
    __shared__ int                s_cidx[CMAX];
    __shared__ unsigned long long s_cand[CMAX];
    __shared__ int   s_nt, s_nc;
    __shared__ float s_eps;

    const int row = blockIdx.x;
    const int tid = threadIdx.x;
    const int wrp = tid >> 5, ln = tid & 31;
    const float4* tm4 = (const float4*)(g_tilemax + (size_t)row * NTM);

    if (tid < EMBED) s_x[tid] = x[(size_t)row * EMBED + tid];
    if (tid == 0) { s_nt = 0; s_nc = 0; }
    __syncthreads();

    // eps = 2.1 * 2^-11 * ||x||2 * 0.1*sqrt(128) = 1.05/1024 * ||x|| * 1.13137
    if (tid < 32) {
        float ss = 0.0f;
        #pragma unroll
        for (int j = 0; j < 4; j++) { float v = s_x[tid * 4 + j]; ss += v * v; }
        #pragma unroll
        for (int o = 16; o > 0; o >>= 1) ss += __shfl_xor_sync(0xFFFFFFFFu, ss, o);
        if (tid == 0) s_eps = 1.05f * (1.0f / 1024.0f) * sqrtf(ss) * 1.1313708f;
    }

    // per-thread group max over 32 contiguous tile-maxima (8 x LDG.128)
    float m = -3.402823466e+38f;
    #pragma unroll
    for (int j = 0; j < 8; j++) {
        const float4 v = tm4[tid * 8 + j];
        m = fmaxf(m, fmaxf(fmaxf(v.x, v.y), fmaxf(v.z, v.w)));
    }
    // block min/max of the 256 group maxima
    float wmx = m, wmn = m;
    #pragma unroll
    for (int o = 16; o > 0; o >>= 1) {
        wmx = fmaxf(wmx, __shfl_xor_sync(0xFFFFFFFFu, wmx, o));
        wmn = fminf(wmn, __shfl_xor_sync(0xFFFFFFFFu, wmn, o));
    }
    if (ln == 0) { s_wmax[wrp] = wmx; s_wmin[wrp] = wmn; }
    __syncthreads();
    float hi = s_wmax[0], lo = s_wmin[0];
    #pragma unroll
    for (int j = 1; j < 8; j++) {
        hi = fmaxf(hi, s_wmax[j]);
        lo = fminf(lo, s_wmin[j]);
    }

    // bisection: invariant cnt(m >= lo) >= 100 (init: all 256 >= min)
    #pragma unroll
    for (int it = 0; it < 20; it++) {
        const float mid = 0.5f * (lo + hi);
        const int cnt = __syncthreads_count(m >= mid);
        if (cnt >= TOPK) lo = mid; else hi = mid;
    }
    const float thr = lo - 1.05f * s_eps - 1e-6f;

    // qualifying tiles (re-scan tm, warp-aggregated append)
    #pragma unroll
    for (int j = 0; j < 8; j++) {
        const float4 v = tm4[tid * 8 + j];
        const int base = tid * 32 + j * 4;
        #pragma unroll
        for (int c = 0; c < 4; c++) {
            const float tv = (c == 0) ? v.x : (c == 1) ? v.y : (c == 2) ? v.z : v.w;
            const bool q = (tv >= thr);
            const int p = wagg_append(&s_nt, q, ln);
            if (q && p < CMAX) s_tiles[p] = base + c;
        }
    }
    __syncthreads();
    const int ntl = s_nt < CMAX ? s_nt : CMAX;

    // candidates within qualifying tiles (fp16 screen values)
    const __half* lg = g_logits + (size_t)row * ITEMS;
    for (int i = wrp; i < ntl; i += TKT / 32) {
        const int idx = s_tiles[i] * TM + ln;
        const float v = __half2float(lg[idx]);
        const bool q = (v >= thr);
        const int p = wagg_append(&s_nc, q, ln);
        if (q && p < CMAX) s_cidx[p] = idx;
    }
    __syncthreads();
    const int C = s_nc < CMAX ? s_nc : CMAX;

    // exact rescore: one thread per candidate, sequential fmaf k=0..127
    for (int i = tid; i < C; i += TKT) {
        const int idx = s_cidx[i];
        const float* wr = w + (size_t)idx * EMBED;
        float s = 0.0f;
        #pragma unroll 8
        for (int k4 = 0; k4 < EMBED / 4; k4++) {
            const float4 wv = ((const float4*)wr)[k4];
            s = fmaf(s_x[k4 * 4 + 0], wv.x, s);
            s = fmaf(s_x[k4 * 4 + 1], wv.y, s);
            s = fmaf(s_x[k4 * 4 + 2], wv.z, s);
            s = fmaf(s_x[k4 * 4 + 3], wv.w, s);
        }
        s_cand[i] = ((unsigned long long)fkey(s) << 32) |
                    (unsigned int)(~(unsigned int)idx);
    }
    __syncthreads();

    int P = 128;
    while (P < C) P <<= 1;
    for (int i = tid; i < P; i += TKT)
        if (i >= C) s_cand[i] = 0ULL;
    __syncthreads();

    // bitonic sort P 64-bit keys desc (value desc, index asc on ties)
    for (int k = 2; k <= P; k <<= 1) {
        for (int j = k >> 1; j > 0; j >>= 1) {
            for (int i = tid; i < P; i += TKT) {
                const int ixj = i ^ j;
                if (ixj > i) {
                    const bool desc = ((i & k) == 0);
                    const unsigned long long a = s_cand[i], b = s_cand[ixj];
                    if (desc ? (a < b) : (a > b)) { s_cand[i] = b; s_cand[ixj] = a; }
                }
            }
            __syncthreads();
        }
    }

    if (tid < TOPK) {
        const unsigned int low = (unsigned int)s_cand[tid];
        out[(size_t)row * TOPK + tid] = (float)(~low);
    }
}

// ---------------------------------------------------------------------------
extern "C" void kernel_launch(void* const* d_in, const int* in_sizes, int n_in,
                              void* d_out, int out_size)
{
    const float* x = nullptr;
    const float* w = nullptr;
    for (int i = 0; i < n_in; i++) {
        if (in_sizes[i] == BATCH * EMBED)      x = (const float*)d_in[i];
        else if (in_sizes[i] == ITEMS * EMBED) w = (const float*)d_in[i];
    }
    float* out = (float*)d_out;

    static bool attr_set = false;
    if (!attr_set) {
        cudaFuncSetAttribute(gemm_screen,
                             cudaFuncAttributeMaxDynamicSharedMemorySize, SM_TOTAL);
        attr_set = true;
    }

    convert_w<<<(ITEMS * EMBED / 8) / 256, 256>>>(w);
    dim3 grid(BATCH / GMB, ITEMS / (NTILE * TPB));   // (8, 256)
    gemm_screen<<<grid, 256, SM_TOTAL>>>(x);
    topk_kernel<<<BATCH, TKT>>>(x, w, out);
}

// round 11
// speedup vs baseline: 6.0084x; 1.0218x over previous
#include <cuda_runtime.h>
#include <cuda_fp16.h>
#include <cstdint>

#define BATCH    1024
#define EMBED    128
#define ITEMS    262144
#define TOPK     100
#define TM       32               // tile-max granularity (items)
#define NTM      (ITEMS/TM)       // 8192 tile maxima per row

#define NTILE    64               // items per GEMM N-tile
#define TPB      16               // N-tiles per CTA
#define GMB      128              // M rows per CTA

__device__ __half g_logits[(size_t)BATCH * ITEMS];
__device__ float  g_tilemax[(size_t)BATCH * NTM];
__device__ __half g_whf[(size_t)ITEMS * EMBED];   // pre-converted w (fp16)

// ---------------------------------------------------------------------------
__device__ __forceinline__ uint32_t smem_u32(const void* p) {
    uint32_t a;
    asm("{ .reg .u64 t; cvta.to.shared.u64 t, %1; cvt.u32.u64 %0, t; }"
        : "=r"(a) : "l"(p));
    return a;
}
__device__ __forceinline__ uint32_t packhf(float lo, float hi) {
    uint32_t r;
    asm("cvt.rn.f16x2.f32 %0, %1, %2;" : "=r"(r) : "f"(hi), "f"(lo));
    return r;
}

#define LDSM4(r0, r1, r2, r3, a)                                              \
    asm volatile("ldmatrix.sync.aligned.m8n8.x4.shared.b16 {%0,%1,%2,%3}, [%4];" \
        : "=r"(r0), "=r"(r1), "=r"(r2), "=r"(r3) : "r"(a))

#define STSM4(a, r0, r1, r2, r3)                                              \
    asm volatile("stmatrix.sync.aligned.m8n8.x4.shared.b16 [%0], {%1,%2,%3,%4};" \
        :: "r"(a), "r"(r0), "r"(r1), "r"(r2), "r"(r3) : "memory")

#define MMA_F16(d, A, b0, b1)                                                 \
    asm volatile("mma.sync.aligned.m16n8k16.row.col.f32.f16.f16.f32 "         \
        "{%0,%1,%2,%3}, {%4,%5,%6,%7}, {%8,%9}, {%0,%1,%2,%3};"               \
        : "+f"((d)[0]), "+f"((d)[1]), "+f"((d)[2]), "+f"((d)[3])              \
        : "r"((A)[0]), "r"((A)[1]), "r"((A)[2]), "r"((A)[3]),                 \
          "r"(b0), "r"(b1))

#define CP_ASYNC16(dst, src)                                                  \
    asm volatile("cp.async.cg.shared.global [%0], [%1], 16;"                  \
        :: "r"(dst), "l"(src) : "memory")
#define CP_COMMIT()  asm volatile("cp.async.commit_group;" ::: "memory")
#define CP_WAIT0()   asm volatile("cp.async.wait_group 0;" ::: "memory")
#define CP_WAIT1()   asm volatile("cp.async.wait_group 1;" ::: "memory")

// ---------------------------------------------------------------------------
// One-time w conversion: fp32 -> fp16 (row-major).
// ---------------------------------------------------------------------------
__global__ __launch_bounds__(256)
void convert_w(const float* __restrict__ w)
{
    const size_t i = (size_t)blockIdx.x * blockDim.x + threadIdx.x; // 8 floats
    const float4* w4 = (const float4*)w;
    const float4 a = w4[i * 2], b = w4[i * 2 + 1];
    ((uint4*)g_whf)[i] = make_uint4(packhf(a.x, a.y), packhf(a.z, a.w),
                                    packhf(b.x, b.y), packhf(b.z, b.w));
}

// ---------------------------------------------------------------------------
// Screening GEMM (2 CTAs/SM): fp16 HMMA, 128(M) x 64(N) x 16 tiles,
// 8 warps (4M x 2N), warp tile 32x32. A resident 32KB; B TRIPLE-buffered
// 3x16KB via cp.async (wait_group 1 -> one tile always in flight);
// stage double-buffered 2x16KB; ONE sync per tile (top of loop).
// smem: A @0 (32K), B @32768 (3x16K), STAGE @81920 (2x16K) = 114688.
// ---------------------------------------------------------------------------
#define SM_B      32768
#define SM_STAGE  81920
#define BTILE_SZ  16384
#define STAGE_SZ  16384
#define SM_TOTAL  114688

__global__ __launch_bounds__(256, 2)
void gemm_screen(const float* __restrict__ x)
{
    extern __shared__ char smem[];
    const uint32_t sb = smem_u32(smem);
    const int tid  = threadIdx.x;
    const int lane = tid & 31;
    const int wid  = tid >> 5;
    const int rowBase   = blockIdx.x * GMB;
    const int itemBase0 = blockIdx.y * (NTILE * TPB);

    int bR[4], bC[4];
    uint32_t bDst[4];
    #pragma unroll
    for (int i = 0; i < 4; i++) {
        const int flat = tid + 256 * i;
        bR[i] = flat >> 4;
        bC[i] = flat & 15;
        bDst[i] = sb + SM_B + bR[i] * 256 + ((bC[i] ^ (bR[i] & 7)) << 4);
    }

    // ---- Stage A (128x128): fp32 -> fp16, 16B-chunk XOR swizzle ----
    const float4* x4 = (const float4*)(x + (size_t)rowBase * EMBED);
    #pragma unroll
    for (int i = 0; i < 8; i++) {
        const int flat = tid + 256 * i;
        const int r = flat >> 4, c = flat & 15;
        const int swc = c ^ (r & 7);
        float4 a0 = x4[flat * 2], a1 = x4[flat * 2 + 1];
        uint4 pa = make_uint4(packhf(a0.x, a0.y), packhf(a0.z, a0.w),
                              packhf(a1.x, a1.y), packhf(a1.z, a1.w));
        *(uint4*)(smem + r * 256 + swc * 16) = pa;
    }

    // ---- cp.async B tiles 0 and 1 (two groups in flight) ----
    #pragma unroll
    for (int i = 0; i < 4; i++) {
        const char* src = (const char*)g_whf
                        + (size_t)(itemBase0 + bR[i]) * 256 + bC[i] * 16;
        CP_ASYNC16(bDst[i], src);
    }
    CP_COMMIT();
    #pragma unroll
    for (int i = 0; i < 4; i++) {
        const char* src = (const char*)g_whf
                        + (size_t)(itemBase0 + NTILE + bR[i]) * 256 + bC[i] * 16;
        CP_ASYNC16(bDst[i] + BTILE_SZ, src);
    }
    CP_COMMIT();

    const int wm = wid >> 1;
    const int wn = wid & 1;
    const int la7  = lane & 7;
    const int lg8  = (lane >> 3) & 1;
    const int cgrp = lane >> 4;

    int Aoff[2], Asw[2];
    #pragma unroll
    for (int a = 0; a < 2; a++) {
        const int rr = wm * 32 + a * 16 + la7 + lg8 * 8;
        Aoff[a] = rr * 256;  Asw[a] = rr & 7;
    }
    int BoffR[2], Bsw[2];
    #pragma unroll
    for (int p = 0; p < 2; p++) {
        const int nr = wn * 32 + p * 16 + la7 + lg8 * 8;
        BoffR[p] = nr * 256;  Bsw[p] = nr & 7;
    }
    const int smRow0 = wm * 32 + lg8 * 8 + la7;
    const int chunk0 = wn * 4 + (lane >> 4);

    for (int n = 0; n < TPB; n++) {
        const int cur3 = n % 3;
        const int itemBase = itemBase0 + n * NTILE;

        // ensure tile n is resident (keep one group in flight), then barrier
        if (n == TPB - 1) CP_WAIT0(); else CP_WAIT1();
        __syncthreads();

        // launch load of tile n+2 into buffer (n+2)%3 (tile n-1's, free now)
        if (n + 2 < TPB) {
            const uint32_t flip = ((n + 2) % 3) * BTILE_SZ;
            #pragma unroll
            for (int i = 0; i < 4; i++) {
                const char* src = (const char*)g_whf
                                + (size_t)(itemBase + 2 * NTILE + bR[i]) * 256
                                + bC[i] * 16;
                CP_ASYNC16(bDst[i] + flip, src);
            }
            CP_COMMIT();
        }

        float d[2][4][4];
        #pragma unroll
        for (int a = 0; a < 2; a++)
            #pragma unroll
            for (int b = 0; b < 4; b++)
                #pragma unroll
                for (int q = 0; q < 4; q++) d[a][b][q] = 0.0f;

        const uint32_t bBase = sb + SM_B + cur3 * BTILE_SZ;
        #pragma unroll
        for (int ks = 0; ks < 8; ks++) {
            const int kc = ks * 2 + cgrp;
            uint32_t A[2][4], B[2][4];
            #pragma unroll
            for (int a = 0; a < 2; a++)
                LDSM4(A[a][0], A[a][1], A[a][2], A[a][3],
                      sb + Aoff[a] + ((kc ^ Asw[a]) << 4));
            #pragma unroll
            for (int p = 0; p < 2; p++)
                LDSM4(B[p][0], B[p][1], B[p][2], B[p][3],
                      bBase + BoffR[p] + ((kc ^ Bsw[p]) << 4));
            #pragma unroll
            for (int a = 0; a < 2; a++)
                #pragma unroll
                for (int b = 0; b < 4; b++)
                    MMA_F16(d[a][b], A[a], B[b >> 1][b & 1], B[b >> 1][(b & 1) + 2]);
        }

        // epilogue: pack + tilemax + stmatrix into stage[n&1]
        const uint32_t stageBase = sb + SM_STAGE + (n & 1) * STAGE_SZ;
        const int colW = itemBase + wn * 32;
        #pragma unroll
        for (int a = 0; a < 2; a++) {
            uint32_t p[8];
            float m1 = -3.402823466e+38f, m2 = m1;
            #pragma unroll
            for (int b = 0; b < 4; b++) {
                p[b * 2 + 0] = packhf(d[a][b][0], d[a][b][1]);
                p[b * 2 + 1] = packhf(d[a][b][2], d[a][b][3]);
                m1 = fmaxf(m1, fmaxf(d[a][b][0], d[a][b][1]));
                m2 = fmaxf(m2, fmaxf(d[a][b][2], d[a][b][3]));
            }
            const int row = smRow0 + a * 16;
            #pragma unroll
            for (int bp = 0; bp < 2; bp++) {
                const int ch = chunk0 + bp * 2;
                const uint32_t addr = stageBase + row * 128
                                    + ((ch ^ (row & 7)) << 4);
                STSM4(addr, p[bp * 4 + 0], p[bp * 4 + 1],
                            p[bp * 4 + 2], p[bp * 4 + 3]);
            }
            m1 = fmaxf(m1, __shfl_xor_sync(0xFFFFFFFFu, m1, 1));
            m1 = fmaxf(m1, __shfl_xor_sync(0xFFFFFFFFu, m1, 2));
            m2 = fmaxf(m2, __shfl_xor_sync(0xFFFFFFFFu, m2, 1));
            m2 = fmaxf(m2, __shfl_xor_sync(0xFFFFFFFFu, m2, 2));
            if ((lane & 3) == 0) {
                const int r1 = rowBase + wm * 32 + a * 16 + (lane >> 2);
                const int grp = colW / TM;
                g_tilemax[(size_t)r1 * NTM + grp]       = m1;
                g_tilemax[(size_t)(r1 + 8) * NTM + grp] = m2;
            }
        }

        // copy-out of tile n-1 from stage[(n-1)&1] (barrier was at loop top)
        if (n >= 1) {
            const char* prev = smem + SM_STAGE + ((n - 1) & 1) * STAGE_SZ;
            const int ib = itemBase - NTILE;
            #pragma unroll
            for (int i = 0; i < 4; i++) {
                const int flat = tid + 256 * i;
                const int r = flat >> 3, c = flat & 7;
                const uint4 v = *(const uint4*)(prev + r * 128
                                                + ((c ^ (r & 7)) << 4));
                *(uint4*)((char*)g_logits
                          + ((size_t)(rowBase + r) * ITEMS + ib) * 2
                          + c * 16) = v;
            }
        }
    }

    // final copy-out: tile TPB-1 (needs a barrier after its stsm)
    __syncthreads();
    {
        const char* prev = smem + SM_STAGE + ((TPB - 1) & 1) * STAGE_SZ;
        const int ib = itemBase0 + (TPB - 1) * NTILE;
        #pragma unroll
        for (int i = 0; i < 4; i++) {
            const int flat = tid + 256 * i;
            const int r = flat >> 3, c = flat & 7;
            const uint4 v = *(const uint4*)(prev + r * 128
                                            + ((c ^ (r & 7)) << 4));
            *(uint4*)((char*)g_logits
                      + ((size_t)(rowBase + r) * ITEMS + ib) * 2
                      + c * 16) = v;
        }
    }
}

// ---------------------------------------------------------------------------
// Top-k. fp16 screen error bound: B = 2^-11 * ||x||2 * 0.1*sqrt(128).
// eps = 2.1*B; threshold via bisection on 256 group maxima with invariant
// cnt(>= lo) >= 100. Exactness chain as before. Gather uses 4-way MLP.
// ---------------------------------------------------------------------------
#define TKT  256
#define CMAX 1024

__device__ __forceinline__ unsigned int fkey(float f) {
    unsigned int b = __float_as_uint(f);
    return b ^ ((b & 0x80000000u) ? 0xFFFFFFFFu : 0x80000000u);
}

__device__ __forceinline__ int wagg_append(int* ctr, bool pred, int ln) {
    const unsigned mask = __ballot_sync(0xFFFFFFFFu, pred);
    if (!pred) return -1;
    const int leader = __ffs(mask) - 1;
    int base = 0;
    if (ln == leader) base = atomicAdd(ctr, __popc(mask));
    base = __shfl_sync(mask, base, leader);
    return base + __popc(mask & ((1u << ln) - 1u));
}

__global__ __launch_bounds__(TKT)
void topk_kernel(const float* __restrict__ x, const float* __restrict__ w,
                 float* __restrict__ out)
{
    __shared__ float              s_x[EMBED];
    __shared__ float              s_wmax[8], s_wmin[8];
    __shared__ int                s_tiles[CMAX];
    __shared__ int                s_cidx[CMAX];
    __shared__ unsigned long long s_cand[CMAX];
    __shared__ int   s_nt, s_nc;
    __shared__ float s_eps;

    const int row = blockIdx.x;
    const int tid = threadIdx.x;
    const int wrp = tid >> 5, ln = tid & 31;
    const float4* tm4 = (const float4*)(g_tilemax + (size_t)row * NTM);

    if (tid < EMBED) s_x[tid] = x[(size_t)row * EMBED + tid];
    if (tid == 0) { s_nt = 0; s_nc = 0; }
    __syncthreads();

    if (tid < 32) {
        float ss = 0.0f;
        #pragma unroll
        for (int j = 0; j < 4; j++) { float v = s_x[tid * 4 + j]; ss += v * v; }
        #pragma unroll
        for (int o = 16; o > 0; o >>= 1) ss += __shfl_xor_sync(0xFFFFFFFFu, ss, o);
        if (tid == 0) s_eps = 1.05f * (1.0f / 1024.0f) * sqrtf(ss) * 1.1313708f;
    }

    // per-thread group max over 32 contiguous tile-maxima (8 x LDG.128)
    float m = -3.402823466e+38f;
    #pragma unroll
    for (int j = 0; j < 8; j++) {
        const float4 v = tm4[tid * 8 + j];
        m = fmaxf(m, fmaxf(fmaxf(v.x, v.y), fmaxf(v.z, v.w)));
    }
    float wmx = m, wmn = m;
    #pragma unroll
    for (int o = 16; o > 0; o >>= 1) {
        wmx = fmaxf(wmx, __shfl_xor_sync(0xFFFFFFFFu, wmx, o));
        wmn = fminf(wmn, __shfl_xor_sync(0xFFFFFFFFu, wmn, o));
    }
    if (ln == 0) { s_wmax[wrp] = wmx; s_wmin[wrp] = wmn; }
    __syncthreads();
    float hi = s_wmax[0], lo = s_wmin[0];
    #pragma unroll
    for (int j = 1; j < 8; j++) {
        hi = fmaxf(hi, s_wmax[j]);
        lo = fminf(lo, s_wmin[j]);
    }

    // bisection: invariant cnt(m >= lo) >= 100
    #pragma unroll
    for (int it = 0; it < 20; it++) {
        const float mid = 0.5f * (lo + hi);
        const int cnt = __syncthreads_count(m >= mid);
        if (cnt >= TOPK) lo = mid; else hi = mid;
    }
    const float thr = lo - 1.05f * s_eps - 1e-6f;

    // qualifying tiles (warp-aggregated append)
    #pragma unroll
    for (int j = 0; j < 8; j++) {
        const float4 v = tm4[tid * 8 + j];
        const int base = tid * 32 + j * 4;
        #pragma unroll
        for (int c = 0; c < 4; c++) {
            const float tv = (c == 0) ? v.x : (c == 1) ? v.y : (c == 2) ? v.z : v.w;
            const bool q = (tv >= thr);
            const int p = wagg_append(&s_nt, q, ln);
            if (q && p < CMAX) s_tiles[p] = base + c;
        }
    }
    __syncthreads();
    const int ntl = s_nt < CMAX ? s_nt : CMAX;

    // candidates within qualifying tiles: 4-way MLP over tiles per warp
    const __half* lg = g_logits + (size_t)row * ITEMS;
    int i = wrp;
    for (; i + 24 < ntl; i += 32) {
        int t0 = s_tiles[i],      t1 = s_tiles[i + 8];
        int t2 = s_tiles[i + 16], t3 = s_tiles[i + 24];
        float v0 = __half2float(lg[t0 * TM + ln]);
        float v1 = __half2float(lg[t1 * TM + ln]);
        float v2 = __half2float(lg[t2 * TM + ln]);
        float v3 = __half2float(lg[t3 * TM + ln]);
        bool q; int p;
        q = (v0 >= thr); p = wagg_append(&s_nc, q, ln);
        if (q && p < CMAX) s_cidx[p] = t0 * TM + ln;
        q = (v1 >= thr); p = wagg_append(&s_nc, q, ln);
        if (q && p < CMAX) s_cidx[p] = t1 * TM + ln;
        q = (v2 >= thr); p = wagg_append(&s_nc, q, ln);
        if (q && p < CMAX) s_cidx[p] = t2 * TM + ln;
        q = (v3 >= thr); p = wagg_append(&s_nc, q, ln);
        if (q && p < CMAX) s_cidx[p] = t3 * TM + ln;
    }
    for (; i < ntl; i += 8) {
        const int idx = s_tiles[i] * TM + ln;
        const float v = __half2float(lg[idx]);
        const bool q = (v >= thr);
        const int p = wagg_append(&s_nc, q, ln);
        if (q && p < CMAX) s_cidx[p] = idx;
    }
    __syncthreads();
    const int C = s_nc < CMAX ? s_nc : CMAX;

    // exact rescore: one thread per candidate, sequential fmaf k=0..127
    for (int i2 = tid; i2 < C; i2 += TKT) {
        const int idx = s_cidx[i2];
        const float* wr = w + (size_t)idx * EMBED;
        float s = 0.0f;
        #pragma unroll 8
        for (int k4 = 0; k4 < EMBED / 4; k4++) {
            const float4 wv = ((const float4*)wr)[k4];
            s = fmaf(s_x[k4 * 4 + 0], wv.x, s);
            s = fmaf(s_x[k4 * 4 + 1], wv.y, s);
            s = fmaf(s_x[k4 * 4 + 2], wv.z, s);
            s = fmaf(s_x[k4 * 4 + 3], wv.w, s);
        }
        s_cand[i2] = ((unsigned long long)fkey(s) << 32) |
                     (unsigned int)(~(unsigned int)idx);
    }
    __syncthreads();

    int P = 128;
    while (P < C) P <<= 1;
    for (int i2 = tid; i2 < P; i2 += TKT)
        if (i2 >= C) s_cand[i2] = 0ULL;
    __syncthreads();

    // bitonic sort P 64-bit keys desc (value desc, index asc on ties)
    for (int k = 2; k <= P; k <<= 1) {
        for (int j = k >> 1; j > 0; j >>= 1) {
            for (int i2 = tid; i2 < P; i2 += TKT) {
                const int ixj = i2 ^ j;
                if (ixj > i2) {
                    const bool desc = ((i2 & k) == 0);
                    const unsigned long long a = s_cand[i2], b = s_cand[ixj];
                    if (desc ? (a < b) : (a > b)) { s_cand[i2] = b; s_cand[ixj] = a; }
                }
            }
            __syncthreads();
        }
    }

    if (tid < TOPK) {
        const unsigned int low = (unsigned int)s_cand[tid];
        out[(size_t)row * TOPK + tid] = (float)(~low);
    }
}

// ---------------------------------------------------------------------------
extern "C" void kernel_launch(void* const* d_in, const int* in_sizes, int n_in,
                              void* d_out, int out_size)
{
    const float* x = nullptr;
    const float* w = nullptr;
    for (int i = 0; i < n_in; i++) {
        if (in_sizes[i] == BATCH * EMBED)      x = (const float*)d_in[i];
        else if (in_sizes[i] == ITEMS * EMBED) w = (const float*)d_in[i];
    }
    float* out = (float*)d_out;

    static bool attr_set = false;
    if (!attr_set) {
        cudaFuncSetAttribute(gemm_screen,
                             cudaFuncAttributeMaxDynamicSharedMemorySize, SM_TOTAL);
        attr_set = true;
    }

    convert_w<<<(ITEMS * EMBED / 8) / 256, 256>>>(w);
    dim3 grid(BATCH / GMB, ITEMS / (NTILE * TPB));   // (8, 256)
    gemm_screen<<<grid, 256, SM_TOTAL>>>(x);
    topk_kernel<<<BATCH, TKT>>>(x, w, out);
}